// round 1
// baseline (speedup 1.0000x reference)
#include <cuda_runtime.h>
#include <math.h>

#define NB 4
#define NT 2048
#define NC 1024
#define NH 128
#define NE 16
#define NN (NB*NT)   // 8192 tokens

// ---------------- scratch (static device allocations; no runtime alloc) ----
static __device__ float g_sn[NC*NE];          // normalized sim matrix
static __device__ float g_sig[NE];            // sigmoid(gates)
static __device__ int   g_nact[NN];
static __device__ unsigned char g_tok_e[NN*NE];
static __device__ float g_tok_w[NN*NE];
static __device__ int   g_cnt[NE];
static __device__ int   g_off[NE];
static __device__ int   g_cur[NE];
static __device__ int   g_pair_tok[NN*NE];
static __device__ float g_pair_w[NN*NE];
static __device__ float g_q[NN*NH];
static __device__ float g_k[NN*NH];
static __device__ float g_v[NN*NH];
static __device__ float g_o[NN*NH];

// ---------------- zero / init ----------------
__global__ void zero_kernel(float* __restrict__ out){
    long i = (long)blockIdx.x*blockDim.x + threadIdx.x;
    long stride = (long)gridDim.x*blockDim.x;
    for(long j=i;j<(long)NN*NH;j+=stride){ g_q[j]=0.f; g_k[j]=0.f; g_v[j]=0.f; }
    for(long j=i;j<(long)NN*NC;j+=stride) out[j]=0.f;
    if(i<NE) g_cnt[(int)i]=0;
}

// ---------------- sim-matrix column normalization + sigmoid(gates) ---------
__global__ void prep_kernel(const float* __restrict__ sim, const float* __restrict__ gates){
    int e = blockIdx.x;
    __shared__ float red[256];
    float ss=0.f;
    for(int c=threadIdx.x;c<NC;c+=256){ float v=sim[c*NE+e]; ss+=v*v; }
    red[threadIdx.x]=ss; __syncthreads();
    for(int s=128;s>0;s>>=1){ if(threadIdx.x<s) red[threadIdx.x]+=red[threadIdx.x+s]; __syncthreads(); }
    float inv = 1.f/fmaxf(sqrtf(red[0]),1e-12f);
    for(int c=threadIdx.x;c<NC;c+=256) g_sn[c*NE+e]=sim[c*NE+e]*inv;
    if(threadIdx.x==0) g_sig[e]=1.f/(1.f+expf(-gates[e]));
}

// ---------------- gating: logits, relu-mask, top-2 fallback, softmax -------
__global__ void __launch_bounds__(128) gate_kernel(const float* __restrict__ X){
    int n = blockIdx.x;
    const float* x = X + (long)n*NC;
    int tid = threadIdx.x;
    float ssq=0.f, dot[NE];
    #pragma unroll
    for(int e=0;e<NE;e++) dot[e]=0.f;
    for(int c=tid;c<NC;c+=128){
        float xv = x[c];
        ssq += xv*xv;
        const float4* sr = (const float4*)(g_sn + c*NE);
        #pragma unroll
        for(int q=0;q<4;q++){
            float4 s4 = sr[q];
            dot[q*4+0]+=xv*s4.x; dot[q*4+1]+=xv*s4.y;
            dot[q*4+2]+=xv*s4.z; dot[q*4+3]+=xv*s4.w;
        }
    }
    #pragma unroll
    for(int off=16;off>0;off>>=1){
        ssq += __shfl_down_sync(0xffffffffu, ssq, off);
        #pragma unroll
        for(int e=0;e<NE;e++) dot[e]+=__shfl_down_sync(0xffffffffu, dot[e], off);
    }
    __shared__ float part[4][NE+1];
    int w = tid>>5, lane = tid&31;
    if(lane==0){ part[w][0]=ssq; for(int e=0;e<NE;e++) part[w][e+1]=dot[e]; }
    __syncthreads();
    if(tid==0){
        float S = part[0][0]+part[1][0]+part[2][0]+part[3][0];
        float inv = 1.f/fmaxf(sqrtf(S),1e-12f);
        float logit[NE];
        #pragma unroll
        for(int e=0;e<NE;e++){
            float d = part[0][e+1]+part[1][e+1]+part[2][e+1]+part[3][e+1];
            logit[e] = d*inv - g_sig[e];
        }
        int act[NE]; int na=0;
        for(int e=0;e<NE;e++) if(logit[e]>0.f) act[na++]=e;
        if(na==0){
            // top-2 fallback (jax top_k: strict > keeps lower index on ties)
            int i1=0;
            for(int e=1;e<NE;e++) if(logit[e]>logit[i1]) i1=e;
            int i2=-1;
            for(int e=0;e<NE;e++) if(e!=i1 && (i2<0 || logit[e]>logit[i2])) i2=e;
            int a = i1<i2? i1:i2; int b2 = i1<i2? i2:i1;
            act[0]=a; act[1]=b2; na=2;
        }
        float vals[NE]; float mx=-1e30f;
        for(int k=0;k<na;k++){ vals[k]=fmaxf(logit[act[k]],0.f); mx=fmaxf(mx,vals[k]); }
        float sum=0.f;
        for(int k=0;k<na;k++){ vals[k]=expf(vals[k]-mx); sum+=vals[k]; }
        float isum = 1.f/sum;
        g_nact[n]=na;
        for(int k=0;k<na;k++){
            g_tok_e[n*NE+k]=(unsigned char)act[k];
            g_tok_w[n*NE+k]=vals[k]*isum;
            atomicAdd(&g_cnt[act[k]],1);
        }
    }
}

__global__ void scan_kernel(){
    if(threadIdx.x==0){
        int o=0;
        for(int e=0;e<NE;e++){ g_off[e]=o; o+=g_cnt[e]; }
    }
    if(threadIdx.x<NE) g_cur[threadIdx.x]=0;
}

__global__ void pairfill_kernel(){
    int n = blockIdx.x*blockDim.x + threadIdx.x;
    if(n>=NN) return;
    int na=g_nact[n];
    for(int k=0;k<na;k++){
        int e=g_tok_e[n*NE+k];
        int s=atomicAdd(&g_cur[e],1);
        int p=g_off[e]+s;
        g_pair_tok[p]=n;
        g_pair_w[p]=g_tok_w[n*NE+k];
    }
}

// ------------- grouped QKV GEMM: gathered X rows @ proj[e], scatter-add ----
__global__ void __launch_bounds__(256) qkv_gemm_kernel(
        const float* __restrict__ X,
        const float* __restrict__ qp,
        const float* __restrict__ kp,
        const float* __restrict__ vp){
    int e = blockIdx.z;
    int cnt = g_cnt[e];
    int m0 = blockIdx.x*64;
    if(m0>=cnt) return;
    int off = g_off[e];
    const float* Bm; float* Out;
    if(blockIdx.y==0){Bm=qp;Out=g_q;} else if(blockIdx.y==1){Bm=kp;Out=g_k;} else {Bm=vp;Out=g_v;}
    Bm += (long)e*NC*NH;

    __shared__ int   stok[64];
    __shared__ float sw[64];
    __shared__ float As[16][64];
    __shared__ float Bs[16][NH];

    int tid=threadIdx.x;
    if(tid<64){
        int m=m0+tid;
        int mm = m<cnt? m : cnt-1;
        stok[tid]=g_pair_tok[off+mm];
        sw[tid]= (m<cnt)? g_pair_w[off+mm] : 0.f;
    }
    __syncthreads();

    int tx=tid&15, ty=tid>>4;
    float acc[4][8];
    #pragma unroll
    for(int i=0;i<4;i++)
        #pragma unroll
        for(int j=0;j<8;j++) acc[i][j]=0.f;

    int lm = tid>>2; int lk=(tid&3)*4;
    const float* arow = X + (long)stok[lm]*NC + lk;
    int bk = tid>>4; int bc=(tid&15)*8;

    for(int k0=0;k0<NC;k0+=16){
        float4 a4 = *(const float4*)(arow + k0);
        As[lk+0][lm]=a4.x; As[lk+1][lm]=a4.y; As[lk+2][lm]=a4.z; As[lk+3][lm]=a4.w;
        const float* brow = Bm + (long)(k0+bk)*NH + bc;
        float4 b0=*(const float4*)brow; float4 b1=*(const float4*)(brow+4);
        *(float4*)&Bs[bk][bc]=b0; *(float4*)&Bs[bk][bc+4]=b1;
        __syncthreads();
        #pragma unroll
        for(int kk=0;kk<16;kk++){
            float4 a  = *(const float4*)&As[kk][ty*4];
            float4 bb0= *(const float4*)&Bs[kk][tx*8];
            float4 bb1= *(const float4*)&Bs[kk][tx*8+4];
            float av[4]={a.x,a.y,a.z,a.w};
            float bv[8]={bb0.x,bb0.y,bb0.z,bb0.w,bb1.x,bb1.y,bb1.z,bb1.w};
            #pragma unroll
            for(int i=0;i<4;i++)
                #pragma unroll
                for(int j=0;j<8;j++) acc[i][j]+=av[i]*bv[j];
        }
        __syncthreads();
    }
    #pragma unroll
    for(int i=0;i<4;i++){
        int r=ty*4+i;
        if(m0+r<cnt){
            float wgt=sw[r];
            long base=(long)stok[r]*NH + tx*8;
            #pragma unroll
            for(int j=0;j<8;j++) atomicAdd(&Out[base+j], acc[i][j]*wgt);
        }
    }
}

// ------------- flash attention, non-causal, H=128, fp32 --------------------
__global__ void __launch_bounds__(256) attn_kernel(){
    extern __shared__ float sm[];
    float* Qs   = sm;                  // 64*129
    float* Ks   = Qs + 64*129;         // 64*129 (reused for V)
    float* Ps   = Ks + 64*129;         // 64*65
    float* red  = Ps + 64*65;          // 64*16
    float* mrow = red + 64*16;         // 64
    float* lrow = mrow + 64;           // 64
    float* arow = lrow + 64;           // 64

    int b=blockIdx.y, qt=blockIdx.x;
    int tid=threadIdx.x, tx=tid&15, ty=tid>>4;
    long qbase = (long)b*NT + (long)qt*64;
    const float scale = 0.0883883476483184f;  // 1/sqrt(128)

    for(int idx=tid; idx<64*128; idx+=256){
        int r=idx>>7, h=idx&127;
        Qs[r*129+h] = g_q[(qbase+r)*NH + h]*scale;
    }
    if(tid<64){ mrow[tid]=-INFINITY; lrow[tid]=0.f; }
    float oacc[4][8];
    #pragma unroll
    for(int i=0;i<4;i++)
        #pragma unroll
        for(int j=0;j<8;j++) oacc[i][j]=0.f;
    __syncthreads();

    for(int kt=0;kt<NT/64;kt++){
        long kbase = (long)b*NT + (long)kt*64;
        for(int idx=tid; idx<64*128; idx+=256){
            int r=idx>>7,h=idx&127;
            Ks[r*129+h]=g_k[(kbase+r)*NH+h];
        }
        __syncthreads();

        float s[4][4];
        #pragma unroll
        for(int i=0;i<4;i++)
            #pragma unroll
            for(int j=0;j<4;j++) s[i][j]=0.f;
        for(int h=0; h<128; h++){
            float qv[4], kv[4];
            #pragma unroll
            for(int i=0;i<4;i++) qv[i]=Qs[(ty*4+i)*129+h];
            #pragma unroll
            for(int j=0;j<4;j++) kv[j]=Ks[(tx+16*j)*129+h];
            #pragma unroll
            for(int i=0;i<4;i++)
                #pragma unroll
                for(int j=0;j<4;j++) s[i][j]+=qv[i]*kv[j];
        }
        #pragma unroll
        for(int i=0;i<4;i++){
            float rm=fmaxf(fmaxf(s[i][0],s[i][1]),fmaxf(s[i][2],s[i][3]));
            red[(ty*4+i)*16+tx]=rm;
        }
        __syncthreads();
        if(tid<64){
            float tm=red[tid*16];
            #pragma unroll
            for(int t=1;t<16;t++) tm=fmaxf(tm,red[tid*16+t]);
            float mo=mrow[tid];
            float mn=fmaxf(mo,tm);
            arow[tid]=expf(mo-mn);
            mrow[tid]=mn;
        }
        __syncthreads();
        #pragma unroll
        for(int i=0;i<4;i++){
            int r=ty*4+i;
            float mn=mrow[r];
            float rs=0.f;
            #pragma unroll
            for(int j=0;j<4;j++){
                float p=expf(s[i][j]-mn);
                Ps[r*65 + tx+16*j]=p;
                rs+=p;
            }
            red[r*16+tx]=rs;
            float al=arow[r];
            #pragma unroll
            for(int j=0;j<8;j++) oacc[i][j]*=al;
        }
        __syncthreads();
        if(tid<64){
            float rs=0.f;
            #pragma unroll
            for(int t=0;t<16;t++) rs+=red[tid*16+t];
            lrow[tid]=lrow[tid]*arow[tid]+rs;
        }
        // overwrite Ks with V tile (safe: S fully consumed before last sync)
        for(int idx=tid; idx<64*128; idx+=256){
            int r=idx>>7,h=idx&127;
            Ks[r*129+h]=g_v[(kbase+r)*NH+h];
        }
        __syncthreads();
        for(int kk=0;kk<64;kk++){
            float pv[4], vv[8];
            #pragma unroll
            for(int i=0;i<4;i++) pv[i]=Ps[(ty*4+i)*65+kk];
            #pragma unroll
            for(int j=0;j<8;j++) vv[j]=Ks[kk*129 + tx+16*j];
            #pragma unroll
            for(int i=0;i<4;i++)
                #pragma unroll
                for(int j=0;j<8;j++) oacc[i][j]+=pv[i]*vv[j];
        }
        __syncthreads();
    }
    #pragma unroll
    for(int i=0;i<4;i++){
        int r=ty*4+i;
        float il=1.f/lrow[r];
        #pragma unroll
        for(int j=0;j<8;j++)
            g_o[(qbase+r)*NH + tx+16*j] = oacc[i][j]*il;
    }
}

// ------------- grouped output GEMM: gathered o rows @ o_proj[e] ------------
__global__ void __launch_bounds__(256) out_gemm_kernel(
        const float* __restrict__ op, float* __restrict__ out){
    int e=blockIdx.z; int cnt=g_cnt[e]; int m0=blockIdx.x*64;
    if(m0>=cnt) return;
    int off=g_off[e];
    int n0=blockIdx.y*NH;  // 8 tiles of 128 over C=1024
    const float* Bm = op + (long)e*NH*NC;

    __shared__ int   stok[64];
    __shared__ float sw[64];
    __shared__ float As[16][64];
    __shared__ float Bs[16][NH];

    int tid=threadIdx.x;
    if(tid<64){
        int m=m0+tid;
        int mm = m<cnt? m : cnt-1;
        stok[tid]=g_pair_tok[off+mm];
        sw[tid]= (m<cnt)? g_pair_w[off+mm] : 0.f;
    }
    __syncthreads();

    int tx=tid&15, ty=tid>>4;
    float acc[4][8];
    #pragma unroll
    for(int i=0;i<4;i++)
        #pragma unroll
        for(int j=0;j<8;j++) acc[i][j]=0.f;

    int lm = tid>>2; int lk=(tid&3)*4;
    const float* arow = g_o + (long)stok[lm]*NH + lk;
    int bk = tid>>4; int bc=(tid&15)*8;

    for(int k0=0;k0<NH;k0+=16){
        float4 a4 = *(const float4*)(arow + k0);
        As[lk+0][lm]=a4.x; As[lk+1][lm]=a4.y; As[lk+2][lm]=a4.z; As[lk+3][lm]=a4.w;
        const float* brow = Bm + (long)(k0+bk)*NC + n0 + bc;
        float4 b0=*(const float4*)brow; float4 b1=*(const float4*)(brow+4);
        *(float4*)&Bs[bk][bc]=b0; *(float4*)&Bs[bk][bc+4]=b1;
        __syncthreads();
        #pragma unroll
        for(int kk=0;kk<16;kk++){
            float4 a  = *(const float4*)&As[kk][ty*4];
            float4 bb0= *(const float4*)&Bs[kk][tx*8];
            float4 bb1= *(const float4*)&Bs[kk][tx*8+4];
            float av[4]={a.x,a.y,a.z,a.w};
            float bv[8]={bb0.x,bb0.y,bb0.z,bb0.w,bb1.x,bb1.y,bb1.z,bb1.w};
            #pragma unroll
            for(int i=0;i<4;i++)
                #pragma unroll
                for(int j=0;j<8;j++) acc[i][j]+=av[i]*bv[j];
        }
        __syncthreads();
    }
    #pragma unroll
    for(int i=0;i<4;i++){
        int r=ty*4+i;
        if(m0+r<cnt){
            float wgt=sw[r];
            long base=(long)stok[r]*NC + n0 + tx*8;
            #pragma unroll
            for(int j=0;j<8;j++) atomicAdd(&out[base+j], acc[i][j]*wgt);
        }
    }
}

// ---------------------------------------------------------------------------
extern "C" void kernel_launch(void* const* d_in, const int* in_sizes, int n_in,
                              void* d_out, int out_size){
    (void)in_sizes; (void)n_in; (void)out_size;
    const float* hs   = (const float*)d_in[0];
    const float* sim  = (const float*)d_in[1];
    const float* gates= (const float*)d_in[2];
    const float* qp   = (const float*)d_in[3];
    const float* kp   = (const float*)d_in[4];
    const float* vp   = (const float*)d_in[5];
    const float* op   = (const float*)d_in[6];
    float* out = (float*)d_out;

    const int attn_smem = (64*129 + 64*129 + 64*65 + 64*16 + 64*3)*sizeof(float);
    cudaFuncSetAttribute(attn_kernel, cudaFuncAttributeMaxDynamicSharedMemorySize, attn_smem);

    zero_kernel<<<2048,256>>>(out);
    prep_kernel<<<NE,256>>>(sim,gates);
    gate_kernel<<<NN,128>>>(hs);
    scan_kernel<<<1,32>>>();
    pairfill_kernel<<<NN/256,256>>>();
    qkv_gemm_kernel<<<dim3(128,3,16),256>>>(hs,qp,kp,vp);
    attn_kernel<<<dim3(NT/64,NB),256,attn_smem>>>();
    out_gemm_kernel<<<dim3(128,8,16),256>>>(op,out);
}

// round 4
// speedup vs baseline: 1.3924x; 1.3924x over previous
#include <cuda_runtime.h>
#include <math.h>
#include <cstdint>

#define NB 4
#define NT 2048
#define NC 1024
#define NH 128
#define NE 16
#define NN (NB*NT)   // 8192 tokens

// ---------------- scratch (static device allocations; no runtime alloc) ----
static __device__ float g_sn[NC*NE];          // normalized sim matrix
static __device__ float g_sig[NE];            // sigmoid(gates)
static __device__ int   g_nact[NN];
static __device__ unsigned char g_tok_e[NN*NE];
static __device__ float g_tok_w[NN*NE];
static __device__ int   g_cnt[NE];
static __device__ int   g_off[NE];
static __device__ int   g_cur[NE];
static __device__ int   g_pair_tok[NN*NE];
static __device__ float g_pair_w[NN*NE];
static __device__ float g_q[NN*NH];
static __device__ float g_k[NN*NH];
static __device__ float g_v[NN*NH];
static __device__ float g_o[NN*NH];

// ================= helpers ==================================================
__device__ __forceinline__ uint32_t smem_u32(const void* p){
    uint32_t a;
    asm("{ .reg .u64 t; cvta.to.shared.u64 t, %1; cvt.u32.u64 %0, t; }" : "=r"(a) : "l"(p));
    return a;
}
#define CP16(dst,src) asm volatile("cp.async.ca.shared.global [%0], [%1], 16;" :: "r"(dst), "l"(src))
#define CP_COMMIT()   asm volatile("cp.async.commit_group;" ::: "memory")
#define CP_WAIT(n)    asm volatile("cp.async.wait_group %0;" :: "n"(n) : "memory")

__device__ __forceinline__ void split_tf32(float x, uint32_t& hi, uint32_t& lo){
    asm("cvt.rna.tf32.f32 %0, %1;" : "=r"(hi) : "f"(x));
    float r = x - __uint_as_float(hi);
    asm("cvt.rna.tf32.f32 %0, %1;" : "=r"(lo) : "f"(r));
}
__device__ __forceinline__ void mma8(float c[4],
        uint32_t a0,uint32_t a1,uint32_t a2,uint32_t a3,
        uint32_t b0,uint32_t b1){
    asm volatile("mma.sync.aligned.m16n8k8.row.col.f32.tf32.tf32.f32 "
        "{%0,%1,%2,%3}, {%4,%5,%6,%7}, {%8,%9}, {%0,%1,%2,%3};"
        : "+f"(c[0]),"+f"(c[1]),"+f"(c[2]),"+f"(c[3])
        : "r"(a0),"r"(a1),"r"(a2),"r"(a3),"r"(b0),"r"(b1));
}

// SMEM layout (bytes) for mma GEMM kernels
#define SOFF_TOK 0            // int[128]
#define SOFF_W   512          // float[128]
#define SOFF_A0  1024         // 128 rows x 40 floats = 20480
#define SOFF_A1  (SOFF_A0+20480)
#define SOFF_B0  (SOFF_A1+20480)   // 32 rows x 136 floats = 17408
#define SOFF_B1  (SOFF_B0+17408)
#define SMEM_MMA_TOTAL (SOFF_B1+17408)   // 76800
#define A_STRIDE 40
#define B_STRIDE 136

// ---------------- zero / init ----------------
__global__ void zero_kernel(float* __restrict__ out){
    long i = (long)blockIdx.x*blockDim.x + threadIdx.x;
    long stride = (long)gridDim.x*blockDim.x;
    for(long j=i;j<(long)NN*NH;j+=stride){ g_q[j]=0.f; g_k[j]=0.f; g_v[j]=0.f; }
    for(long j=i;j<(long)NN*NC;j+=stride) out[j]=0.f;
    if(i<NE) g_cnt[(int)i]=0;
}

// ---------------- sim-matrix column normalization + sigmoid(gates) ---------
__global__ void prep_kernel(const float* __restrict__ sim, const float* __restrict__ gates){
    int e = blockIdx.x;
    __shared__ float red[256];
    float ss=0.f;
    for(int c=threadIdx.x;c<NC;c+=256){ float v=sim[c*NE+e]; ss+=v*v; }
    red[threadIdx.x]=ss; __syncthreads();
    for(int s=128;s>0;s>>=1){ if(threadIdx.x<s) red[threadIdx.x]+=red[threadIdx.x+s]; __syncthreads(); }
    float inv = 1.f/fmaxf(sqrtf(red[0]),1e-12f);
    for(int c=threadIdx.x;c<NC;c+=256) g_sn[c*NE+e]=sim[c*NE+e]*inv;
    if(threadIdx.x==0) g_sig[e]=1.f/(1.f+expf(-gates[e]));
}

// ---------------- gating ----------------
__global__ void __launch_bounds__(128) gate_kernel(const float* __restrict__ X){
    int n = blockIdx.x;
    const float* x = X + (long)n*NC;
    int tid = threadIdx.x;
    float ssq=0.f, dot[NE];
    #pragma unroll
    for(int e=0;e<NE;e++) dot[e]=0.f;
    for(int c=tid;c<NC;c+=128){
        float xv = x[c];
        ssq += xv*xv;
        const float4* sr = (const float4*)(g_sn + c*NE);
        #pragma unroll
        for(int q=0;q<4;q++){
            float4 s4 = sr[q];
            dot[q*4+0]+=xv*s4.x; dot[q*4+1]+=xv*s4.y;
            dot[q*4+2]+=xv*s4.z; dot[q*4+3]+=xv*s4.w;
        }
    }
    #pragma unroll
    for(int off=16;off>0;off>>=1){
        ssq += __shfl_down_sync(0xffffffffu, ssq, off);
        #pragma unroll
        for(int e=0;e<NE;e++) dot[e]+=__shfl_down_sync(0xffffffffu, dot[e], off);
    }
    __shared__ float part[4][NE+1];
    int w = tid>>5, lane = tid&31;
    if(lane==0){ part[w][0]=ssq; for(int e=0;e<NE;e++) part[w][e+1]=dot[e]; }
    __syncthreads();
    if(tid==0){
        float S = part[0][0]+part[1][0]+part[2][0]+part[3][0];
        float inv = 1.f/fmaxf(sqrtf(S),1e-12f);
        float logit[NE];
        #pragma unroll
        for(int e=0;e<NE;e++){
            float d = part[0][e+1]+part[1][e+1]+part[2][e+1]+part[3][e+1];
            logit[e] = d*inv - g_sig[e];
        }
        int act[NE]; int na=0;
        for(int e=0;e<NE;e++) if(logit[e]>0.f) act[na++]=e;
        if(na==0){
            int i1=0;
            for(int e=1;e<NE;e++) if(logit[e]>logit[i1]) i1=e;
            int i2=-1;
            for(int e=0;e<NE;e++) if(e!=i1 && (i2<0 || logit[e]>logit[i2])) i2=e;
            int a = i1<i2? i1:i2; int b2 = i1<i2? i2:i1;
            act[0]=a; act[1]=b2; na=2;
        }
        float vals[NE]; float mx=-1e30f;
        for(int k=0;k<na;k++){ vals[k]=fmaxf(logit[act[k]],0.f); mx=fmaxf(mx,vals[k]); }
        float sum=0.f;
        for(int k=0;k<na;k++){ vals[k]=expf(vals[k]-mx); sum+=vals[k]; }
        float isum = 1.f/sum;
        g_nact[n]=na;
        for(int k=0;k<na;k++){
            g_tok_e[n*NE+k]=(unsigned char)act[k];
            g_tok_w[n*NE+k]=vals[k]*isum;
            atomicAdd(&g_cnt[act[k]],1);
        }
    }
}

__global__ void scan_kernel(){
    if(threadIdx.x==0){
        int o=0;
        for(int e=0;e<NE;e++){ g_off[e]=o; o+=g_cnt[e]; }
    }
    if(threadIdx.x<NE) g_cur[threadIdx.x]=0;
}

__global__ void pairfill_kernel(){
    int n = blockIdx.x*blockDim.x + threadIdx.x;
    if(n>=NN) return;
    int na=g_nact[n];
    for(int k=0;k<na;k++){
        int e=g_tok_e[n*NE+k];
        int s=atomicAdd(&g_cur[e],1);
        int p=g_off[e]+s;
        g_pair_tok[p]=n;
        g_pair_w[p]=g_tok_w[n*NE+k];
    }
}

// =============== 3xTF32 mma.sync grouped GEMM ==============================
// CTA: 128 gathered rows x 128 out cols. 8 warps, warp tile 64x32.
// QKV=1: A = hidden_states (host ptr), blockIdx.y selects q/k/v, out -> g_q/k/v.
// QKV=0: A = g_o (device symbol, resolved IN KERNEL), out -> d_out n-tile.
template<int KTOT, int LDA, int LDB, int LDO, int QKV>
__global__ void __launch_bounds__(256) mma_gemm_kernel(
        const float* __restrict__ AglIn,
        const float* __restrict__ Bq,
        const float* __restrict__ Bk,
        const float* __restrict__ Bv,
        float* __restrict__ OutP){
    int e = blockIdx.z;
    int cnt = g_cnt[e];
    int m0 = blockIdx.x*128;
    if(m0>=cnt) return;
    int off = g_off[e];

    const float* Agl;
    const float* Bsrc; float* Out; int n0;
    if(QKV){
        Agl = AglIn;
        n0 = 0;
        if(blockIdx.y==0){Bsrc=Bq;Out=g_q;}
        else if(blockIdx.y==1){Bsrc=Bk;Out=g_k;}
        else {Bsrc=Bv;Out=g_v;}
        Bsrc += (long)e*KTOT*LDB;
    } else {
        Agl = g_o;                      // device-symbol resolved in device code
        n0 = blockIdx.y*128;
        Bsrc = Bq + (long)e*KTOT*LDB;
        Out = OutP;
    }

    extern __shared__ __align__(16) char smem[];
    uint32_t sb = smem_u32(smem);
    int*   stok = (int*)(smem + SOFF_TOK);
    float* sw   = (float*)(smem + SOFF_W);

    int tid=threadIdx.x, lane=tid&31, wid=tid>>5;
    int wr = wid>>2;          // 0..1 -> m offset wr*64
    int wc = wid&3;           // 0..3 -> n offset wc*32

    if(tid<128){
        int m=m0+tid; int mm = m<cnt? m : cnt-1;
        stok[tid]=g_pair_tok[off+mm];
        sw[tid]= (m<cnt)? g_pair_w[off+mm] : 0.f;
    }
    __syncthreads();

    // per-thread copy assignments
    int arow_r = tid>>1, arow_h = tid&1;
    const float* asrc_base = Agl + (long)stok[arow_r]*LDA + arow_h*16;
    uint32_t adst_off = (uint32_t)(arow_r*(A_STRIDE*4) + arow_h*64);

    const int NCH = KTOT/32;

    // ---- prefetch chunk 0 ----
    {
        uint32_t sa = sb + SOFF_A0;
        uint32_t sB = sb + SOFF_B0;
        const float* as = asrc_base;
        #pragma unroll
        for(int q=0;q<4;q++) CP16(sa + adst_off + q*16, as + q*4);
        #pragma unroll
        for(int i=0;i<4;i++){
            int u = tid + i*256;
            int kk = u>>5, cg = u&31;
            CP16(sB + kk*(B_STRIDE*4) + cg*16, Bsrc + (long)kk*LDB + n0 + cg*4);
        }
        CP_COMMIT();
    }

    float acc[4][4][4];
    #pragma unroll
    for(int mf=0;mf<4;mf++)
        #pragma unroll
        for(int nf=0;nf<4;nf++)
            #pragma unroll
            for(int u=0;u<4;u++) acc[mf][nf][u]=0.f;

    for(int c=0;c<NCH;c++){
        if(c+1<NCH){
            uint32_t sa = sb + ((c+1)&1 ? SOFF_A1 : SOFF_A0);
            uint32_t sB = sb + ((c+1)&1 ? SOFF_B1 : SOFF_B0);
            const float* as = asrc_base + (c+1)*32;
            const float* bs = Bsrc + (long)(c+1)*32*LDB + n0;
            #pragma unroll
            for(int q=0;q<4;q++) CP16(sa + adst_off + q*16, as + q*4);
            #pragma unroll
            for(int i=0;i<4;i++){
                int u = tid + i*256;
                int kk = u>>5, cg = u&31;
                CP16(sB + kk*(B_STRIDE*4) + cg*16, bs + (long)kk*LDB + cg*4);
            }
            CP_COMMIT();
            CP_WAIT(1);
        } else {
            CP_WAIT(0);
        }
        __syncthreads();

        const float* As = (const float*)(smem + ((c&1)?SOFF_A1:SOFF_A0));
        const float* Bs = (const float*)(smem + ((c&1)?SOFF_B1:SOFF_B0));

        #pragma unroll
        for(int s=0;s<4;s++){
            uint32_t ahi[4][4], alo[4][4];
            int acol = s*8 + (lane&3);
            #pragma unroll
            for(int mf=0;mf<4;mf++){
                int row = wr*64 + mf*16 + (lane>>2);
                float f0 = As[row*A_STRIDE + acol];
                float f1 = As[(row+8)*A_STRIDE + acol];
                float f2 = As[row*A_STRIDE + acol + 4];
                float f3 = As[(row+8)*A_STRIDE + acol + 4];
                split_tf32(f0, ahi[mf][0], alo[mf][0]);
                split_tf32(f1, ahi[mf][1], alo[mf][1]);
                split_tf32(f2, ahi[mf][2], alo[mf][2]);
                split_tf32(f3, ahi[mf][3], alo[mf][3]);
            }
            int brow = s*8 + (lane&3);
            #pragma unroll
            for(int nf=0;nf<4;nf++){
                int ncol = wc*32 + nf*8 + (lane>>2);
                float g0 = Bs[brow*B_STRIDE + ncol];
                float g1 = Bs[(brow+4)*B_STRIDE + ncol];
                uint32_t bh0,bl0,bh1,bl1;
                split_tf32(g0, bh0, bl0);
                split_tf32(g1, bh1, bl1);
                #pragma unroll
                for(int mf=0;mf<4;mf++){
                    mma8(acc[mf][nf], ahi[mf][0],ahi[mf][1],ahi[mf][2],ahi[mf][3], bh0,bh1);
                    mma8(acc[mf][nf], ahi[mf][0],ahi[mf][1],ahi[mf][2],ahi[mf][3], bl0,bl1);
                    mma8(acc[mf][nf], alo[mf][0],alo[mf][1],alo[mf][2],alo[mf][3], bh0,bh1);
                }
            }
        }
        __syncthreads();
    }

    // ---- epilogue: weight-scale + atomic scatter ----
    #pragma unroll
    for(int mf=0;mf<4;mf++){
        int r0 = wr*64 + mf*16 + (lane>>2);
        int r1 = r0 + 8;
        float w0 = sw[r0], w1 = sw[r1];
        int live0 = (m0 + r0 < cnt), live1 = (m0 + r1 < cnt);
        long b0 = (long)stok[r0]*LDO + n0;
        long b1 = (long)stok[r1]*LDO + n0;
        #pragma unroll
        for(int nf=0;nf<4;nf++){
            int col = wc*32 + nf*8 + (lane&3)*2;
            if(live0){
                atomicAdd(&Out[b0 + col    ], acc[mf][nf][0]*w0);
                atomicAdd(&Out[b0 + col + 1], acc[mf][nf][1]*w0);
            }
            if(live1){
                atomicAdd(&Out[b1 + col    ], acc[mf][nf][2]*w1);
                atomicAdd(&Out[b1 + col + 1], acc[mf][nf][3]*w1);
            }
        }
    }
}

// ------------- flash attention, non-causal, H=128, fp32 --------------------
__global__ void __launch_bounds__(256) attn_kernel(){
    extern __shared__ float sm[];
    float* Qs   = sm;                  // 64*129
    float* Ks   = Qs + 64*129;         // 64*129 (reused for V)
    float* Ps   = Ks + 64*129;         // 64*65
    float* red  = Ps + 64*65;          // 64*16
    float* mrow = red + 64*16;         // 64
    float* lrow = mrow + 64;           // 64
    float* arow = lrow + 64;           // 64

    int b=blockIdx.y, qt=blockIdx.x;
    int tid=threadIdx.x, tx=tid&15, ty=tid>>4;
    long qbase = (long)b*NT + (long)qt*64;
    const float scale = 0.0883883476483184f;  // 1/sqrt(128)

    for(int idx=tid; idx<64*128; idx+=256){
        int r=idx>>7, h=idx&127;
        Qs[r*129+h] = g_q[(qbase+r)*NH + h]*scale;
    }
    if(tid<64){ mrow[tid]=-INFINITY; lrow[tid]=0.f; }
    float oacc[4][8];
    #pragma unroll
    for(int i=0;i<4;i++)
        #pragma unroll
        for(int j=0;j<8;j++) oacc[i][j]=0.f;
    __syncthreads();

    for(int kt=0;kt<NT/64;kt++){
        long kbase = (long)b*NT + (long)kt*64;
        for(int idx=tid; idx<64*128; idx+=256){
            int r=idx>>7,h=idx&127;
            Ks[r*129+h]=g_k[(kbase+r)*NH+h];
        }
        __syncthreads();

        float s[4][4];
        #pragma unroll
        for(int i=0;i<4;i++)
            #pragma unroll
            for(int j=0;j<4;j++) s[i][j]=0.f;
        for(int h=0; h<128; h++){
            float qv[4], kv[4];
            #pragma unroll
            for(int i=0;i<4;i++) qv[i]=Qs[(ty*4+i)*129+h];
            #pragma unroll
            for(int j=0;j<4;j++) kv[j]=Ks[(tx+16*j)*129+h];
            #pragma unroll
            for(int i=0;i<4;i++)
                #pragma unroll
                for(int j=0;j<4;j++) s[i][j]+=qv[i]*kv[j];
        }
        #pragma unroll
        for(int i=0;i<4;i++){
            float rm=fmaxf(fmaxf(s[i][0],s[i][1]),fmaxf(s[i][2],s[i][3]));
            red[(ty*4+i)*16+tx]=rm;
        }
        __syncthreads();
        if(tid<64){
            float tm=red[tid*16];
            #pragma unroll
            for(int t=1;t<16;t++) tm=fmaxf(tm,red[tid*16+t]);
            float mo=mrow[tid];
            float mn=fmaxf(mo,tm);
            arow[tid]=expf(mo-mn);
            mrow[tid]=mn;
        }
        __syncthreads();
        #pragma unroll
        for(int i=0;i<4;i++){
            int r=ty*4+i;
            float mn=mrow[r];
            float rs=0.f;
            #pragma unroll
            for(int j=0;j<4;j++){
                float p=expf(s[i][j]-mn);
                Ps[r*65 + tx+16*j]=p;
                rs+=p;
            }
            red[r*16+tx]=rs;
            float al=arow[r];
            #pragma unroll
            for(int j=0;j<8;j++) oacc[i][j]*=al;
        }
        __syncthreads();
        if(tid<64){
            float rs=0.f;
            #pragma unroll
            for(int t=0;t<16;t++) rs+=red[tid*16+t];
            lrow[tid]=lrow[tid]*arow[tid]+rs;
        }
        for(int idx=tid; idx<64*128; idx+=256){
            int r=idx>>7,h=idx&127;
            Ks[r*129+h]=g_v[(kbase+r)*NH+h];
        }
        __syncthreads();
        for(int kk=0;kk<64;kk++){
            float pv[4], vv[8];
            #pragma unroll
            for(int i=0;i<4;i++) pv[i]=Ps[(ty*4+i)*65+kk];
            #pragma unroll
            for(int j=0;j<8;j++) vv[j]=Ks[kk*129 + tx+16*j];
            #pragma unroll
            for(int i=0;i<4;i++)
                #pragma unroll
                for(int j=0;j<8;j++) oacc[i][j]+=pv[i]*vv[j];
        }
        __syncthreads();
    }
    #pragma unroll
    for(int i=0;i<4;i++){
        int r=ty*4+i;
        float il=1.f/lrow[r];
        #pragma unroll
        for(int j=0;j<8;j++)
            g_o[(qbase+r)*NH + tx+16*j] = oacc[i][j]*il;
    }
}

// ---------------------------------------------------------------------------
extern "C" void kernel_launch(void* const* d_in, const int* in_sizes, int n_in,
                              void* d_out, int out_size){
    (void)in_sizes; (void)n_in; (void)out_size;
    const float* hs   = (const float*)d_in[0];
    const float* sim  = (const float*)d_in[1];
    const float* gates= (const float*)d_in[2];
    const float* qp   = (const float*)d_in[3];
    const float* kp   = (const float*)d_in[4];
    const float* vp   = (const float*)d_in[5];
    const float* op   = (const float*)d_in[6];
    float* out = (float*)d_out;

    const int attn_smem = (64*129 + 64*129 + 64*65 + 64*16 + 64*3)*sizeof(float);
    cudaFuncSetAttribute(attn_kernel, cudaFuncAttributeMaxDynamicSharedMemorySize, attn_smem);
    cudaFuncSetAttribute(mma_gemm_kernel<NC,NC,NH,NH,1>, cudaFuncAttributeMaxDynamicSharedMemorySize, SMEM_MMA_TOTAL);
    cudaFuncSetAttribute(mma_gemm_kernel<NH,NH,NC,NC,0>, cudaFuncAttributeMaxDynamicSharedMemorySize, SMEM_MMA_TOTAL);

    zero_kernel<<<2048,256>>>(out);
    prep_kernel<<<NE,256>>>(sim,gates);
    gate_kernel<<<NN,128>>>(hs);
    scan_kernel<<<1,32>>>();
    pairfill_kernel<<<NN/256,256>>>();
    // QKV: grid x = 64 m-tiles (covers up to 8192 rows/expert), y = 3 projections, z = experts
    mma_gemm_kernel<NC,NC,NH,NH,1><<<dim3(64,3,16),256,SMEM_MMA_TOTAL>>>(hs,qp,kp,vp,nullptr);
    attn_kernel<<<dim3(NT/64,NB),256,attn_smem>>>();
    // OUT: grid x = 64 m-tiles, y = 8 n-tiles of 128 (C=1024), z = experts; A resolved in-kernel (g_o)
    mma_gemm_kernel<NH,NH,NC,NC,0><<<dim3(64,8,16),256,SMEM_MMA_TOTAL>>>(nullptr,op,nullptr,nullptr,out);
}

// round 6
// speedup vs baseline: 1.5273x; 1.0969x over previous
#include <cuda_runtime.h>
#include <math.h>
#include <cstdint>

#define NB 4
#define NT 2048
#define NC 1024
#define NH 128
#define NE 16
#define NN (NB*NT)   // 8192 tokens

// ---------------- scratch (static device allocations; no runtime alloc) ----
static __device__ float g_sn[NC*NE];          // normalized sim matrix
static __device__ float g_sig[NE];            // sigmoid(gates)
static __device__ int   g_nact[NN];
static __device__ unsigned char g_tok_e[NN*NE];
static __device__ float g_tok_w[NN*NE];
static __device__ int   g_cnt[NE];
static __device__ int   g_off[NE];
static __device__ int   g_cur[NE];
static __device__ int   g_pair_tok[NN*NE];
static __device__ float g_pair_w[NN*NE];
static __device__ float g_q[NN*NH];
static __device__ float g_k[NN*NH];
static __device__ float g_v[NN*NH];
static __device__ float g_o[NN*NH];

// ================= helpers ==================================================
__device__ __forceinline__ uint32_t smem_u32(const void* p){
    uint32_t a;
    asm("{ .reg .u64 t; cvta.to.shared.u64 t, %1; cvt.u32.u64 %0, t; }" : "=r"(a) : "l"(p));
    return a;
}
#define CP16(dst,src) asm volatile("cp.async.ca.shared.global [%0], [%1], 16;" :: "r"(dst), "l"(src))
#define CP_COMMIT()   asm volatile("cp.async.commit_group;" ::: "memory")
#define CP_WAIT(n)    asm volatile("cp.async.wait_group %0;" :: "n"(n) : "memory")

__device__ __forceinline__ void split_tf32(float x, uint32_t& hi, uint32_t& lo){
    asm("cvt.rna.tf32.f32 %0, %1;" : "=r"(hi) : "f"(x));
    float r = x - __uint_as_float(hi);
    asm("cvt.rna.tf32.f32 %0, %1;" : "=r"(lo) : "f"(r));
}
__device__ __forceinline__ void mma8(float c[4],
        uint32_t a0,uint32_t a1,uint32_t a2,uint32_t a3,
        uint32_t b0,uint32_t b1){
    asm volatile("mma.sync.aligned.m16n8k8.row.col.f32.tf32.tf32.f32 "
        "{%0,%1,%2,%3}, {%4,%5,%6,%7}, {%8,%9}, {%0,%1,%2,%3};"
        : "+f"(c[0]),"+f"(c[1]),"+f"(c[2]),"+f"(c[3])
        : "r"(a0),"r"(a1),"r"(a2),"r"(a3),"r"(b0),"r"(b1));
}

// SMEM layout (bytes) for mma GEMM kernels
#define SOFF_TOK 0            // int[128]
#define SOFF_W   512          // float[128]
#define SOFF_A0  1024         // 128 rows x 40 floats = 20480
#define SOFF_A1  (SOFF_A0+20480)
#define SOFF_B0  (SOFF_A1+20480)   // 32 rows x 136 floats = 17408
#define SOFF_B1  (SOFF_B0+17408)
#define SMEM_MMA_TOTAL (SOFF_B1+17408)   // 76800
#define A_STRIDE 40
#define B_STRIDE 136

// ---------------- zero / init ----------------
__global__ void zero_kernel(float* __restrict__ out){
    long i = (long)blockIdx.x*blockDim.x + threadIdx.x;
    long stride = (long)gridDim.x*blockDim.x;
    for(long j=i;j<(long)NN*NH;j+=stride){ g_q[j]=0.f; g_k[j]=0.f; g_v[j]=0.f; }
    for(long j=i;j<(long)NN*NC;j+=stride) out[j]=0.f;
    if(i<NE) g_cnt[(int)i]=0;
}

// ---------------- sim-matrix column normalization + sigmoid(gates) ---------
__global__ void prep_kernel(const float* __restrict__ sim, const float* __restrict__ gates){
    int e = blockIdx.x;
    __shared__ float red[256];
    float ss=0.f;
    for(int c=threadIdx.x;c<NC;c+=256){ float v=sim[c*NE+e]; ss+=v*v; }
    red[threadIdx.x]=ss; __syncthreads();
    for(int s=128;s>0;s>>=1){ if(threadIdx.x<s) red[threadIdx.x]+=red[threadIdx.x+s]; __syncthreads(); }
    float inv = 1.f/fmaxf(sqrtf(red[0]),1e-12f);
    for(int c=threadIdx.x;c<NC;c+=256) g_sn[c*NE+e]=sim[c*NE+e]*inv;
    if(threadIdx.x==0) g_sig[e]=1.f/(1.f+expf(-gates[e]));
}

// ---------------- gating ----------------
__global__ void __launch_bounds__(128) gate_kernel(const float* __restrict__ X){
    int n = blockIdx.x;
    const float* x = X + (long)n*NC;
    int tid = threadIdx.x;
    float ssq=0.f, dot[NE];
    #pragma unroll
    for(int e=0;e<NE;e++) dot[e]=0.f;
    for(int c=tid;c<NC;c+=128){
        float xv = x[c];
        ssq += xv*xv;
        const float4* sr = (const float4*)(g_sn + c*NE);
        #pragma unroll
        for(int q=0;q<4;q++){
            float4 s4 = sr[q];
            dot[q*4+0]+=xv*s4.x; dot[q*4+1]+=xv*s4.y;
            dot[q*4+2]+=xv*s4.z; dot[q*4+3]+=xv*s4.w;
        }
    }
    #pragma unroll
    for(int off=16;off>0;off>>=1){
        ssq += __shfl_down_sync(0xffffffffu, ssq, off);
        #pragma unroll
        for(int e=0;e<NE;e++) dot[e]+=__shfl_down_sync(0xffffffffu, dot[e], off);
    }
    __shared__ float part[4][NE+1];
    int w = tid>>5, lane = tid&31;
    if(lane==0){ part[w][0]=ssq; for(int e=0;e<NE;e++) part[w][e+1]=dot[e]; }
    __syncthreads();
    if(tid==0){
        float S = part[0][0]+part[1][0]+part[2][0]+part[3][0];
        float inv = 1.f/fmaxf(sqrtf(S),1e-12f);
        float logit[NE];
        #pragma unroll
        for(int e=0;e<NE;e++){
            float d = part[0][e+1]+part[1][e+1]+part[2][e+1]+part[3][e+1];
            logit[e] = d*inv - g_sig[e];
        }
        int act[NE]; int na=0;
        for(int e=0;e<NE;e++) if(logit[e]>0.f) act[na++]=e;
        if(na==0){
            int i1=0;
            for(int e=1;e<NE;e++) if(logit[e]>logit[i1]) i1=e;
            int i2=-1;
            for(int e=0;e<NE;e++) if(e!=i1 && (i2<0 || logit[e]>logit[i2])) i2=e;
            int a = i1<i2? i1:i2; int b2 = i1<i2? i2:i1;
            act[0]=a; act[1]=b2; na=2;
        }
        float vals[NE]; float mx=-1e30f;
        for(int k=0;k<na;k++){ vals[k]=fmaxf(logit[act[k]],0.f); mx=fmaxf(mx,vals[k]); }
        float sum=0.f;
        for(int k=0;k<na;k++){ vals[k]=expf(vals[k]-mx); sum+=vals[k]; }
        float isum = 1.f/sum;
        g_nact[n]=na;
        for(int k=0;k<na;k++){
            g_tok_e[n*NE+k]=(unsigned char)act[k];
            g_tok_w[n*NE+k]=vals[k]*isum;
            atomicAdd(&g_cnt[act[k]],1);
        }
    }
}

__global__ void scan_kernel(){
    if(threadIdx.x==0){
        int o=0;
        for(int e=0;e<NE;e++){ g_off[e]=o; o+=g_cnt[e]; }
    }
    if(threadIdx.x<NE) g_cur[threadIdx.x]=0;
}

__global__ void pairfill_kernel(){
    int n = blockIdx.x*blockDim.x + threadIdx.x;
    if(n>=NN) return;
    int na=g_nact[n];
    for(int k=0;k<na;k++){
        int e=g_tok_e[n*NE+k];
        int s=atomicAdd(&g_cur[e],1);
        int p=g_off[e]+s;
        g_pair_tok[p]=n;
        g_pair_w[p]=g_tok_w[n*NE+k];
    }
}

// =============== 3xTF32 mma.sync grouped GEMM ==============================
template<int KTOT, int LDA, int LDB, int LDO, int QKV>
__global__ void __launch_bounds__(256) mma_gemm_kernel(
        const float* __restrict__ AglIn,
        const float* __restrict__ Bq,
        const float* __restrict__ Bk,
        const float* __restrict__ Bv,
        float* __restrict__ OutP){
    int e = blockIdx.z;
    int cnt = g_cnt[e];
    int m0 = blockIdx.x*128;
    if(m0>=cnt) return;
    int off = g_off[e];

    const float* Agl;
    const float* Bsrc; float* Out; int n0;
    if(QKV){
        Agl = AglIn;
        n0 = 0;
        if(blockIdx.y==0){Bsrc=Bq;Out=g_q;}
        else if(blockIdx.y==1){Bsrc=Bk;Out=g_k;}
        else {Bsrc=Bv;Out=g_v;}
        Bsrc += (long)e*KTOT*LDB;
    } else {
        Agl = g_o;                      // device-symbol resolved in device code
        n0 = blockIdx.y*128;
        Bsrc = Bq + (long)e*KTOT*LDB;
        Out = OutP;
    }

    extern __shared__ __align__(16) char smem[];
    uint32_t sb = smem_u32(smem);
    int*   stok = (int*)(smem + SOFF_TOK);
    float* sw   = (float*)(smem + SOFF_W);

    int tid=threadIdx.x, lane=tid&31, wid=tid>>5;
    int wr = wid>>2;          // 0..1 -> m offset wr*64
    int wc = wid&3;           // 0..3 -> n offset wc*32

    if(tid<128){
        int m=m0+tid; int mm = m<cnt? m : cnt-1;
        stok[tid]=g_pair_tok[off+mm];
        sw[tid]= (m<cnt)? g_pair_w[off+mm] : 0.f;
    }
    __syncthreads();

    int arow_r = tid>>1, arow_h = tid&1;
    const float* asrc_base = Agl + (long)stok[arow_r]*LDA + arow_h*16;
    uint32_t adst_off = (uint32_t)(arow_r*(A_STRIDE*4) + arow_h*64);

    const int NCH = KTOT/32;

    {
        uint32_t sa = sb + SOFF_A0;
        uint32_t sB = sb + SOFF_B0;
        const float* as = asrc_base;
        #pragma unroll
        for(int q=0;q<4;q++) CP16(sa + adst_off + q*16, as + q*4);
        #pragma unroll
        for(int i=0;i<4;i++){
            int u = tid + i*256;
            int kk = u>>5, cg = u&31;
            CP16(sB + kk*(B_STRIDE*4) + cg*16, Bsrc + (long)kk*LDB + n0 + cg*4);
        }
        CP_COMMIT();
    }

    float acc[4][4][4];
    #pragma unroll
    for(int mf=0;mf<4;mf++)
        #pragma unroll
        for(int nf=0;nf<4;nf++)
            #pragma unroll
            for(int u=0;u<4;u++) acc[mf][nf][u]=0.f;

    for(int c=0;c<NCH;c++){
        if(c+1<NCH){
            uint32_t sa = sb + ((c+1)&1 ? SOFF_A1 : SOFF_A0);
            uint32_t sB = sb + ((c+1)&1 ? SOFF_B1 : SOFF_B0);
            const float* as = asrc_base + (c+1)*32;
            const float* bs = Bsrc + (long)(c+1)*32*LDB + n0;
            #pragma unroll
            for(int q=0;q<4;q++) CP16(sa + adst_off + q*16, as + q*4);
            #pragma unroll
            for(int i=0;i<4;i++){
                int u = tid + i*256;
                int kk = u>>5, cg = u&31;
                CP16(sB + kk*(B_STRIDE*4) + cg*16, bs + (long)kk*LDB + cg*4);
            }
            CP_COMMIT();
            CP_WAIT(1);
        } else {
            CP_WAIT(0);
        }
        __syncthreads();

        const float* As = (const float*)(smem + ((c&1)?SOFF_A1:SOFF_A0));
        const float* Bs = (const float*)(smem + ((c&1)?SOFF_B1:SOFF_B0));

        #pragma unroll
        for(int s=0;s<4;s++){
            uint32_t ahi[4][4], alo[4][4];
            int acol = s*8 + (lane&3);
            #pragma unroll
            for(int mf=0;mf<4;mf++){
                int row = wr*64 + mf*16 + (lane>>2);
                float f0 = As[row*A_STRIDE + acol];
                float f1 = As[(row+8)*A_STRIDE + acol];
                float f2 = As[row*A_STRIDE + acol + 4];
                float f3 = As[(row+8)*A_STRIDE + acol + 4];
                split_tf32(f0, ahi[mf][0], alo[mf][0]);
                split_tf32(f1, ahi[mf][1], alo[mf][1]);
                split_tf32(f2, ahi[mf][2], alo[mf][2]);
                split_tf32(f3, ahi[mf][3], alo[mf][3]);
            }
            int brow = s*8 + (lane&3);
            #pragma unroll
            for(int nf=0;nf<4;nf++){
                int ncol = wc*32 + nf*8 + (lane>>2);
                float g0 = Bs[brow*B_STRIDE + ncol];
                float g1 = Bs[(brow+4)*B_STRIDE + ncol];
                uint32_t bh0,bl0,bh1,bl1;
                split_tf32(g0, bh0, bl0);
                split_tf32(g1, bh1, bl1);
                #pragma unroll
                for(int mf=0;mf<4;mf++){
                    mma8(acc[mf][nf], ahi[mf][0],ahi[mf][1],ahi[mf][2],ahi[mf][3], bh0,bh1);
                    mma8(acc[mf][nf], ahi[mf][0],ahi[mf][1],ahi[mf][2],ahi[mf][3], bl0,bl1);
                    mma8(acc[mf][nf], alo[mf][0],alo[mf][1],alo[mf][2],alo[mf][3], bh0,bh1);
                }
            }
        }
        __syncthreads();
    }

    #pragma unroll
    for(int mf=0;mf<4;mf++){
        int r0 = wr*64 + mf*16 + (lane>>2);
        int r1 = r0 + 8;
        float w0 = sw[r0], w1 = sw[r1];
        int live0 = (m0 + r0 < cnt), live1 = (m0 + r1 < cnt);
        long b0 = (long)stok[r0]*LDO + n0;
        long b1 = (long)stok[r1]*LDO + n0;
        #pragma unroll
        for(int nf=0;nf<4;nf++){
            int col = wc*32 + nf*8 + (lane&3)*2;
            if(live0){
                atomicAdd(&Out[b0 + col    ], acc[mf][nf][0]*w0);
                atomicAdd(&Out[b0 + col + 1], acc[mf][nf][1]*w0);
            }
            if(live1){
                atomicAdd(&Out[b1 + col    ], acc[mf][nf][2]*w1);
                atomicAdd(&Out[b1 + col + 1], acc[mf][nf][3]*w1);
            }
        }
    }
}

// ------------- flash attention with 3xTF32 mma, H=128 ----------------------
// CTA: 64 q rows, 256 threads, 8 warps.
// S phase (64x64):   warps 4x2, warp tile 16x32 (mf=1, nf=4)
// PV phase (64x128): warps 4x2, warp tile 16x64 (mf=1, nf=8)
// Q/K/V pre-split hi/lo in smem (stride 136), P split at write (stride 72).
#define AQS 136
#define APS 72
#define AOFF_QH 0
#define AOFF_QL 8704
#define AOFF_KH 17408
#define AOFF_KL 26112
#define AOFF_PH 34816
#define AOFF_PL 39424
#define AOFF_RM 44032
#define AOFF_RL 44160
#define AOFF_MR 44288
#define AOFF_LR 44352
#define AOFF_AR 44416
#define ATTN_SMEM_FLOATS 44480

__global__ void __launch_bounds__(256) attn_tc_kernel(){
    extern __shared__ float sm[];
    float* Qh = sm + AOFF_QH; float* Ql = sm + AOFF_QL;
    float* Kh = sm + AOFF_KH; float* Kl = sm + AOFF_KL;   // reused for V
    float* Ph = sm + AOFF_PH; float* Pl = sm + AOFF_PL;
    float* redm = sm + AOFF_RM; float* redl = sm + AOFF_RL;
    float* mrow = sm + AOFF_MR; float* lrow = sm + AOFF_LR; float* arow = sm + AOFF_AR;

    int b = blockIdx.y, qt = blockIdx.x;
    int tid = threadIdx.x, lane = tid&31, wid = tid>>5;
    int wr = wid>>1, wc = wid&1;
    long qbase = (long)b*NT + (long)qt*64;
    const float scale = 0.0883883476483184f;   // 1/sqrt(128)

    // load + split Q (scaled)
    for(int idx=tid; idx<64*128; idx+=256){
        int r = idx>>7, h = idx&127;
        float v = g_q[(qbase+r)*NH + h]*scale;
        uint32_t hi, lo; split_tf32(v, hi, lo);
        Qh[r*AQS+h] = __uint_as_float(hi);
        Ql[r*AQS+h] = __uint_as_float(lo);
    }
    if(tid<64){ mrow[tid]=-INFINITY; lrow[tid]=0.f; }

    float oacc[8][4];
    #pragma unroll
    for(int nf=0;nf<8;nf++)
        #pragma unroll
        for(int u=0;u<4;u++) oacc[nf][u]=0.f;

    int am = wr*16 + (lane>>2);        // warp m-row base for frags
    int r0 = am, r1 = am+8;            // accumulator rows for this thread
    __syncthreads();

    for(int kt=0; kt<NT/64; kt++){
        long kbase = (long)b*NT + (long)kt*64;
        // load + split K tile
        for(int idx=tid; idx<64*128; idx+=256){
            int r=idx>>7, h=idx&127;
            float v = g_k[(kbase+r)*NH+h];
            uint32_t hi,lo; split_tf32(v,hi,lo);
            Kh[r*AQS+h]=__uint_as_float(hi);
            Kl[r*AQS+h]=__uint_as_float(lo);
        }
        __syncthreads();

        // ---- S = Q K^T (3xTF32) ----
        float sacc[4][4];
        #pragma unroll
        for(int nf=0;nf<4;nf++)
            #pragma unroll
            for(int u=0;u<4;u++) sacc[nf][u]=0.f;

        #pragma unroll
        for(int s=0;s<16;s++){
            int ac = s*8 + (lane&3);
            uint32_t ah0=__float_as_uint(Qh[r0*AQS+ac]);
            uint32_t ah1=__float_as_uint(Qh[r1*AQS+ac]);
            uint32_t ah2=__float_as_uint(Qh[r0*AQS+ac+4]);
            uint32_t ah3=__float_as_uint(Qh[r1*AQS+ac+4]);
            uint32_t al0=__float_as_uint(Ql[r0*AQS+ac]);
            uint32_t al1=__float_as_uint(Ql[r1*AQS+ac]);
            uint32_t al2=__float_as_uint(Ql[r0*AQS+ac+4]);
            uint32_t al3=__float_as_uint(Ql[r1*AQS+ac+4]);
            #pragma unroll
            for(int nf=0;nf<4;nf++){
                int nrow = wc*32 + nf*8 + (lane>>2);
                uint32_t bh0=__float_as_uint(Kh[nrow*AQS + ac]);
                uint32_t bh1=__float_as_uint(Kh[nrow*AQS + ac+4]);
                uint32_t bl0=__float_as_uint(Kl[nrow*AQS + ac]);
                uint32_t bl1=__float_as_uint(Kl[nrow*AQS + ac+4]);
                mma8(sacc[nf], ah0,ah1,ah2,ah3, bh0,bh1);
                mma8(sacc[nf], ah0,ah1,ah2,ah3, bl0,bl1);
                mma8(sacc[nf], al0,al1,al2,al3, bh0,bh1);
            }
        }

        // ---- row max ----
        float pm0 = fmaxf(fmaxf(sacc[0][0],sacc[0][1]), fmaxf(sacc[1][0],sacc[1][1]));
        pm0 = fmaxf(pm0, fmaxf(fmaxf(sacc[2][0],sacc[2][1]), fmaxf(sacc[3][0],sacc[3][1])));
        float pm1 = fmaxf(fmaxf(sacc[0][2],sacc[0][3]), fmaxf(sacc[1][2],sacc[1][3]));
        pm1 = fmaxf(pm1, fmaxf(fmaxf(sacc[2][2],sacc[2][3]), fmaxf(sacc[3][2],sacc[3][3])));
        pm0 = fmaxf(pm0, __shfl_xor_sync(0xffffffffu, pm0, 1));
        pm0 = fmaxf(pm0, __shfl_xor_sync(0xffffffffu, pm0, 2));
        pm1 = fmaxf(pm1, __shfl_xor_sync(0xffffffffu, pm1, 1));
        pm1 = fmaxf(pm1, __shfl_xor_sync(0xffffffffu, pm1, 2));
        if((lane&3)==0){
            redm[wc*64 + r0] = pm0;
            redm[wc*64 + r1] = pm1;
        }
        __syncthreads();
        if(tid<64){
            float mo = mrow[tid];
            float mn = fmaxf(mo, fmaxf(redm[tid], redm[64+tid]));
            arow[tid] = expf(mo - mn);
            mrow[tid] = mn;
        }
        __syncthreads();

        // ---- P = exp(S - m), split to smem; partial row sums; rescale oacc --
        float mn0 = mrow[r0], mn1 = mrow[r1];
        float a0 = arow[r0], a1 = arow[r1];
        float rs0=0.f, rs1=0.f;
        #pragma unroll
        for(int nf=0;nf<4;nf++){
            int col = wc*32 + nf*8 + (lane&3)*2;
            float p0 = expf(sacc[nf][0]-mn0);
            float p1 = expf(sacc[nf][1]-mn0);
            float p2 = expf(sacc[nf][2]-mn1);
            float p3 = expf(sacc[nf][3]-mn1);
            rs0 += p0+p1; rs1 += p2+p3;
            uint32_t hi,lo;
            split_tf32(p0,hi,lo); Ph[r0*APS+col  ]=__uint_as_float(hi); Pl[r0*APS+col  ]=__uint_as_float(lo);
            split_tf32(p1,hi,lo); Ph[r0*APS+col+1]=__uint_as_float(hi); Pl[r0*APS+col+1]=__uint_as_float(lo);
            split_tf32(p2,hi,lo); Ph[r1*APS+col  ]=__uint_as_float(hi); Pl[r1*APS+col  ]=__uint_as_float(lo);
            split_tf32(p3,hi,lo); Ph[r1*APS+col+1]=__uint_as_float(hi); Pl[r1*APS+col+1]=__uint_as_float(lo);
        }
        rs0 += __shfl_xor_sync(0xffffffffu, rs0, 1);
        rs0 += __shfl_xor_sync(0xffffffffu, rs0, 2);
        rs1 += __shfl_xor_sync(0xffffffffu, rs1, 1);
        rs1 += __shfl_xor_sync(0xffffffffu, rs1, 2);
        if((lane&3)==0){
            redl[wc*64 + r0] = rs0;
            redl[wc*64 + r1] = rs1;
        }
        #pragma unroll
        for(int nf=0;nf<8;nf++){
            oacc[nf][0]*=a0; oacc[nf][1]*=a0;
            oacc[nf][2]*=a1; oacc[nf][3]*=a1;
        }
        __syncthreads();

        // ---- lrow update + load V tile (overwrites K buffers) ----
        if(tid<64) lrow[tid] = lrow[tid]*arow[tid] + redl[tid] + redl[64+tid];
        for(int idx=tid; idx<64*128; idx+=256){
            int r=idx>>7, h=idx&127;
            float v = g_v[(kbase+r)*NH+h];
            uint32_t hi,lo; split_tf32(v,hi,lo);
            Kh[r*AQS+h]=__uint_as_float(hi);
            Kl[r*AQS+h]=__uint_as_float(lo);
        }
        __syncthreads();

        // ---- O += P V (3xTF32) ----
        #pragma unroll
        for(int s=0;s<8;s++){
            int ac = s*8 + (lane&3);
            uint32_t ah0=__float_as_uint(Ph[r0*APS+ac]);
            uint32_t ah1=__float_as_uint(Ph[r1*APS+ac]);
            uint32_t ah2=__float_as_uint(Ph[r0*APS+ac+4]);
            uint32_t ah3=__float_as_uint(Ph[r1*APS+ac+4]);
            uint32_t al0=__float_as_uint(Pl[r0*APS+ac]);
            uint32_t al1=__float_as_uint(Pl[r1*APS+ac]);
            uint32_t al2=__float_as_uint(Pl[r0*APS+ac+4]);
            uint32_t al3=__float_as_uint(Pl[r1*APS+ac+4]);
            #pragma unroll
            for(int nf=0;nf<8;nf++){
                int ncol = wc*64 + nf*8 + (lane>>2);
                uint32_t bh0=__float_as_uint(Kh[ac*AQS + ncol]);
                uint32_t bh1=__float_as_uint(Kh[(ac+4)*AQS + ncol]);
                uint32_t bl0=__float_as_uint(Kl[ac*AQS + ncol]);
                uint32_t bl1=__float_as_uint(Kl[(ac+4)*AQS + ncol]);
                mma8(oacc[nf], ah0,ah1,ah2,ah3, bh0,bh1);
                mma8(oacc[nf], ah0,ah1,ah2,ah3, bl0,bl1);
                mma8(oacc[nf], al0,al1,al2,al3, bh0,bh1);
            }
        }
        __syncthreads();
    }

    // ---- epilogue: normalize + store ----
    float il0 = 1.f/lrow[r0], il1 = 1.f/lrow[r1];
    #pragma unroll
    for(int nf=0;nf<8;nf++){
        int col = wc*64 + nf*8 + (lane&3)*2;
        g_o[(qbase+r0)*NH + col    ] = oacc[nf][0]*il0;
        g_o[(qbase+r0)*NH + col + 1] = oacc[nf][1]*il0;
        g_o[(qbase+r1)*NH + col    ] = oacc[nf][2]*il1;
        g_o[(qbase+r1)*NH + col + 1] = oacc[nf][3]*il1;
    }
}

// ---------------------------------------------------------------------------
extern "C" void kernel_launch(void* const* d_in, const int* in_sizes, int n_in,
                              void* d_out, int out_size){
    (void)in_sizes; (void)n_in; (void)out_size;
    const float* hs   = (const float*)d_in[0];
    const float* sim  = (const float*)d_in[1];
    const float* gates= (const float*)d_in[2];
    const float* qp   = (const float*)d_in[3];
    const float* kp   = (const float*)d_in[4];
    const float* vp   = (const float*)d_in[5];
    const float* op   = (const float*)d_in[6];
    float* out = (float*)d_out;

    const int attn_smem = ATTN_SMEM_FLOATS*sizeof(float);   // 177920
    cudaFuncSetAttribute(attn_tc_kernel, cudaFuncAttributeMaxDynamicSharedMemorySize, attn_smem);
    cudaFuncSetAttribute(mma_gemm_kernel<NC,NC,NH,NH,1>, cudaFuncAttributeMaxDynamicSharedMemorySize, SMEM_MMA_TOTAL);
    cudaFuncSetAttribute(mma_gemm_kernel<NH,NH,NC,NC,0>, cudaFuncAttributeMaxDynamicSharedMemorySize, SMEM_MMA_TOTAL);

    zero_kernel<<<2048,256>>>(out);
    prep_kernel<<<NE,256>>>(sim,gates);
    gate_kernel<<<NN,128>>>(hs);
    scan_kernel<<<1,32>>>();
    pairfill_kernel<<<NN/256,256>>>();
    mma_gemm_kernel<NC,NC,NH,NH,1><<<dim3(64,3,16),256,SMEM_MMA_TOTAL>>>(hs,qp,kp,vp,nullptr);
    attn_tc_kernel<<<dim3(NT/64,NB),256,attn_smem>>>();
    mma_gemm_kernel<NH,NH,NC,NC,0><<<dim3(64,8,16),256,SMEM_MMA_TOTAL>>>(nullptr,op,nullptr,nullptr,out);
}

// round 7
// speedup vs baseline: 2.5411x; 1.6638x over previous
#include <cuda_runtime.h>
#include <cuda_bf16.h>
#include <math.h>
#include <cstdint>

#define NB 4
#define NT 2048
#define NC 1024
#define NH 128
#define NE 16
#define NN (NB*NT)   // 8192 tokens

// ---------------- scratch (static device allocations; no runtime alloc) ----
static __device__ float g_sn[NC*NE];
static __device__ float g_sig[NE];
static __device__ int   g_nact[NN];
static __device__ unsigned char g_tok_e[NN*NE];
static __device__ float g_tok_w[NN*NE];
static __device__ int   g_cnt[NE];
static __device__ int   g_off[NE];
static __device__ int   g_cur[NE];
static __device__ int   g_pair_tok[NN*NE];
static __device__ float g_pair_w[NN*NE];
static __device__ float g_q[NN*NH];
static __device__ float g_k[NN*NH];
static __device__ float g_v[NN*NH];
static __device__ float g_o[NN*NH];

// ================= helpers ==================================================
__device__ __forceinline__ uint32_t smem_u32(const void* p){
    uint32_t a;
    asm("{ .reg .u64 t; cvta.to.shared.u64 t, %1; cvt.u32.u64 %0, t; }" : "=r"(a) : "l"(p));
    return a;
}
// split a float pair into bf16x2 hi word + bf16x2 lo word (low half = first elem)
__device__ __forceinline__ void split_pair(float x, float y, uint32_t& hi, uint32_t& lo){
    __nv_bfloat162 h = __floats2bfloat162_rn(x, y);
    float rx = x - __low2float(h);
    float ry = y - __high2float(h);
    __nv_bfloat162 l = __floats2bfloat162_rn(rx, ry);
    hi = *(uint32_t*)&h;
    lo = *(uint32_t*)&l;
}
#define LDM4(r0,r1,r2,r3,addr) \
    asm volatile("ldmatrix.sync.aligned.m8n8.x4.shared.b16 {%0,%1,%2,%3}, [%4];" \
        : "=r"(r0),"=r"(r1),"=r"(r2),"=r"(r3) : "r"(addr))
#define LDM4T(r0,r1,r2,r3,addr) \
    asm volatile("ldmatrix.sync.aligned.m8n8.x4.trans.shared.b16 {%0,%1,%2,%3}, [%4];" \
        : "=r"(r0),"=r"(r1),"=r"(r2),"=r"(r3) : "r"(addr))
__device__ __forceinline__ void mma16(float c[4],
        uint32_t a0,uint32_t a1,uint32_t a2,uint32_t a3,
        uint32_t b0,uint32_t b1){
    asm volatile("mma.sync.aligned.m16n8k16.row.col.f32.bf16.bf16.f32 "
        "{%0,%1,%2,%3}, {%4,%5,%6,%7}, {%8,%9}, {%0,%1,%2,%3};"
        : "+f"(c[0]),"+f"(c[1]),"+f"(c[2]),"+f"(c[3])
        : "r"(a0),"r"(a1),"r"(a2),"r"(a3),"r"(b0),"r"(b1));
}

// ---------------- zero / init ----------------
__global__ void zero_kernel(float* __restrict__ out){
    long i = (long)blockIdx.x*blockDim.x + threadIdx.x;
    long stride = (long)gridDim.x*blockDim.x;
    for(long j=i;j<(long)NN*NH;j+=stride){ g_q[j]=0.f; g_k[j]=0.f; g_v[j]=0.f; }
    for(long j=i;j<(long)NN*NC;j+=stride) out[j]=0.f;
    if(i<NE) g_cnt[(int)i]=0;
}

// ---------------- sim-matrix column normalization + sigmoid(gates) ---------
__global__ void prep_kernel(const float* __restrict__ sim, const float* __restrict__ gates){
    int e = blockIdx.x;
    __shared__ float red[256];
    float ss=0.f;
    for(int c=threadIdx.x;c<NC;c+=256){ float v=sim[c*NE+e]; ss+=v*v; }
    red[threadIdx.x]=ss; __syncthreads();
    for(int s=128;s>0;s>>=1){ if(threadIdx.x<s) red[threadIdx.x]+=red[threadIdx.x+s]; __syncthreads(); }
    float inv = 1.f/fmaxf(sqrtf(red[0]),1e-12f);
    for(int c=threadIdx.x;c<NC;c+=256) g_sn[c*NE+e]=sim[c*NE+e]*inv;
    if(threadIdx.x==0) g_sig[e]=1.f/(1.f+expf(-gates[e]));
}

// ---------------- gating ----------------
__global__ void __launch_bounds__(128) gate_kernel(const float* __restrict__ X){
    int n = blockIdx.x;
    const float* x = X + (long)n*NC;
    int tid = threadIdx.x;
    float ssq=0.f, dot[NE];
    #pragma unroll
    for(int e=0;e<NE;e++) dot[e]=0.f;
    for(int c=tid;c<NC;c+=128){
        float xv = x[c];
        ssq += xv*xv;
        const float4* sr = (const float4*)(g_sn + c*NE);
        #pragma unroll
        for(int q=0;q<4;q++){
            float4 s4 = sr[q];
            dot[q*4+0]+=xv*s4.x; dot[q*4+1]+=xv*s4.y;
            dot[q*4+2]+=xv*s4.z; dot[q*4+3]+=xv*s4.w;
        }
    }
    #pragma unroll
    for(int off=16;off>0;off>>=1){
        ssq += __shfl_down_sync(0xffffffffu, ssq, off);
        #pragma unroll
        for(int e=0;e<NE;e++) dot[e]+=__shfl_down_sync(0xffffffffu, dot[e], off);
    }
    __shared__ float part[4][NE+1];
    int w = tid>>5, lane = tid&31;
    if(lane==0){ part[w][0]=ssq; for(int e=0;e<NE;e++) part[w][e+1]=dot[e]; }
    __syncthreads();
    if(tid==0){
        float S = part[0][0]+part[1][0]+part[2][0]+part[3][0];
        float inv = 1.f/fmaxf(sqrtf(S),1e-12f);
        float logit[NE];
        #pragma unroll
        for(int e=0;e<NE;e++){
            float d = part[0][e+1]+part[1][e+1]+part[2][e+1]+part[3][e+1];
            logit[e] = d*inv - g_sig[e];
        }
        int act[NE]; int na=0;
        for(int e=0;e<NE;e++) if(logit[e]>0.f) act[na++]=e;
        if(na==0){
            int i1=0;
            for(int e=1;e<NE;e++) if(logit[e]>logit[i1]) i1=e;
            int i2=-1;
            for(int e=0;e<NE;e++) if(e!=i1 && (i2<0 || logit[e]>logit[i2])) i2=e;
            int a = i1<i2? i1:i2; int b2 = i1<i2? i2:i1;
            act[0]=a; act[1]=b2; na=2;
        }
        float vals[NE]; float mx=-1e30f;
        for(int k=0;k<na;k++){ vals[k]=fmaxf(logit[act[k]],0.f); mx=fmaxf(mx,vals[k]); }
        float sum=0.f;
        for(int k=0;k<na;k++){ vals[k]=expf(vals[k]-mx); sum+=vals[k]; }
        float isum = 1.f/sum;
        g_nact[n]=na;
        for(int k=0;k<na;k++){
            g_tok_e[n*NE+k]=(unsigned char)act[k];
            g_tok_w[n*NE+k]=vals[k]*isum;
            atomicAdd(&g_cnt[act[k]],1);
        }
    }
}

__global__ void scan_kernel(){
    if(threadIdx.x==0){
        int o=0;
        for(int e=0;e<NE;e++){ g_off[e]=o; o+=g_cnt[e]; }
    }
    if(threadIdx.x<NE) g_cur[threadIdx.x]=0;
}

__global__ void pairfill_kernel(){
    int n = blockIdx.x*blockDim.x + threadIdx.x;
    if(n>=NN) return;
    int na=g_nact[n];
    for(int k=0;k<na;k++){
        int e=g_tok_e[n*NE+k];
        int s=atomicAdd(&g_cur[e],1);
        int p=g_off[e]+s;
        g_pair_tok[p]=n;
        g_pair_w[p]=g_tok_w[n*NE+k];
    }
}

// =============== 3xBF16 m16n8k16 grouped GEMM ==============================
// CTA: 128 gathered rows x 128 out cols, 8 warps (warp tile 64x32), k-chunks of 32.
// A smem: [128 m][32 k] bf16, row stride 80B (hi + lo buffers)
// B smem: [32 k][128 n] bf16, row stride 272B (hi + lo) -> ldmatrix.x4.trans
#define GS_TOK 0
#define GS_W   512
#define GS_AH  1024
#define GS_AL  (GS_AH+10240)
#define GS_BH  (GS_AL+10240)
#define GS_BL  (GS_BH+8704)
#define GS_TOTAL (GS_BL+8704)   // 38912

template<int KTOT, int LDA, int LDB, int LDO, int QKV>
__global__ void __launch_bounds__(256) bf16_gemm_kernel(
        const float* __restrict__ AglIn,
        const float* __restrict__ Bq,
        const float* __restrict__ Bk,
        const float* __restrict__ Bv,
        float* __restrict__ OutP){
    int e = blockIdx.z;
    int cnt = g_cnt[e];
    int m0 = blockIdx.x*128;
    if(m0>=cnt) return;
    int off = g_off[e];

    const float* Agl;
    const float* Bsrc; float* Out; int n0;
    if(QKV){
        Agl = AglIn; n0 = 0;
        if(blockIdx.y==0){Bsrc=Bq;Out=g_q;}
        else if(blockIdx.y==1){Bsrc=Bk;Out=g_k;}
        else {Bsrc=Bv;Out=g_v;}
        Bsrc += (long)e*KTOT*LDB;
    } else {
        Agl = g_o;
        n0 = blockIdx.y*128;
        Bsrc = Bq + (long)e*KTOT*LDB;
        Out = OutP;
    }

    extern __shared__ __align__(16) char smem[];
    uint32_t sb = smem_u32(smem);
    int*   stok = (int*)(smem + GS_TOK);
    float* sw   = (float*)(smem + GS_W);

    int tid=threadIdx.x, lane=tid&31, wid=tid>>5;
    int wr = wid>>2, wc = wid&3;

    if(tid<128){
        int m=m0+tid; int mm = m<cnt? m : cnt-1;
        stok[tid]=g_pair_tok[off+mm];
        sw[tid]= (m<cnt)? g_pair_w[off+mm] : 0.f;
    }
    __syncthreads();

    // load assignments
    int ar = tid>>1, ah = tid&1;
    const float* asrc = Agl + (long)stok[ar]*LDA + ah*16;
    int adst = GS_AH + ar*80 + ah*32;
    int bk = tid>>3, bn = (tid&7)*16;
    const float* bsrc0 = Bsrc + (long)bk*LDB + n0 + bn;
    int bdst = GS_BH + bk*272 + bn*2;

    // ldmatrix addresses
    int mid = lane>>3, l7 = lane&7;
    uint32_t aAddr[4];
    #pragma unroll
    for(int mf=0;mf<4;mf++){
        int row = wr*64 + mf*16 + (mid&1)*8 + l7;
        aAddr[mf] = sb + GS_AH + row*80 + (mid>>1)*16;
    }
    uint32_t bAddr[2];
    #pragma unroll
    for(int g=0;g<2;g++){
        int krow = (mid&1)*8 + l7;
        int ncol = wc*32 + g*16 + (mid>>1)*8;
        bAddr[g] = sb + GS_BH + krow*272 + ncol*2;
    }

    float acc[4][4][4];
    #pragma unroll
    for(int mf=0;mf<4;mf++)
        #pragma unroll
        for(int nf=0;nf<4;nf++)
            #pragma unroll
            for(int u=0;u<4;u++) acc[mf][nf][u]=0.f;

    const int NCH = KTOT/32;
    for(int c=0;c<NCH;c++){
        if(c) __syncthreads();
        // A tile
        {
            const float* as = asrc + c*32;
            #pragma unroll
            for(int q=0;q<4;q++){
                float4 v = *(const float4*)(as + q*4);
                uint32_t h0,l0,h1,l1;
                split_pair(v.x,v.y,h0,l0);
                split_pair(v.z,v.w,h1,l1);
                *(uint2*)(smem + adst + q*8) = make_uint2(h0,h1);
                *(uint2*)(smem + adst + (GS_AL-GS_AH) + q*8) = make_uint2(l0,l1);
            }
        }
        // B tile
        {
            const float* bs = bsrc0 + (long)c*32*LDB;
            #pragma unroll
            for(int q=0;q<4;q++){
                float4 v = *(const float4*)(bs + q*4);
                uint32_t h0,l0,h1,l1;
                split_pair(v.x,v.y,h0,l0);
                split_pair(v.z,v.w,h1,l1);
                *(uint2*)(smem + bdst + q*8) = make_uint2(h0,h1);
                *(uint2*)(smem + bdst + (GS_BL-GS_BH) + q*8) = make_uint2(l0,l1);
            }
        }
        __syncthreads();

        #pragma unroll
        for(int s=0;s<2;s++){
            uint32_t ahh[4][4], alo[4][4];
            #pragma unroll
            for(int mf=0;mf<4;mf++){
                LDM4(ahh[mf][0],ahh[mf][1],ahh[mf][2],ahh[mf][3], aAddr[mf] + s*32);
                LDM4(alo[mf][0],alo[mf][1],alo[mf][2],alo[mf][3], aAddr[mf] + (GS_AL-GS_AH) + s*32);
            }
            #pragma unroll
            for(int g=0;g<2;g++){
                uint32_t bh[4], bl[4];
                LDM4T(bh[0],bh[1],bh[2],bh[3], bAddr[g] + s*4352);
                LDM4T(bl[0],bl[1],bl[2],bl[3], bAddr[g] + (GS_BL-GS_BH) + s*4352);
                #pragma unroll
                for(int sub=0;sub<2;sub++){
                    #pragma unroll
                    for(int mf=0;mf<4;mf++){
                        float* C = acc[mf][g*2+sub];
                        mma16(C, ahh[mf][0],ahh[mf][1],ahh[mf][2],ahh[mf][3], bh[sub*2],bh[sub*2+1]);
                        mma16(C, ahh[mf][0],ahh[mf][1],ahh[mf][2],ahh[mf][3], bl[sub*2],bl[sub*2+1]);
                        mma16(C, alo[mf][0],alo[mf][1],alo[mf][2],alo[mf][3], bh[sub*2],bh[sub*2+1]);
                    }
                }
            }
        }
    }

    // epilogue: weight-scale + atomic scatter
    #pragma unroll
    for(int mf=0;mf<4;mf++){
        int r0 = wr*64 + mf*16 + (lane>>2);
        int r1 = r0 + 8;
        float w0 = sw[r0], w1 = sw[r1];
        int live0 = (m0 + r0 < cnt), live1 = (m0 + r1 < cnt);
        long b0 = (long)stok[r0]*LDO + n0;
        long b1 = (long)stok[r1]*LDO + n0;
        #pragma unroll
        for(int nf=0;nf<4;nf++){
            int col = wc*32 + nf*8 + (lane&3)*2;
            if(live0){
                atomicAdd(&Out[b0 + col    ], acc[mf][nf][0]*w0);
                atomicAdd(&Out[b0 + col + 1], acc[mf][nf][1]*w0);
            }
            if(live1){
                atomicAdd(&Out[b1 + col    ], acc[mf][nf][2]*w1);
                atomicAdd(&Out[b1 + col + 1], acc[mf][nf][3]*w1);
            }
        }
    }
}

// ------------- flash attention, 3xBF16 mma + ldmatrix, H=128 ---------------
// CTA 64 q rows, 8 warps: wr=wid>>1 (m16 tile), wc=wid&1 (n half).
// Q,K,V smem [row][128] bf16 stride 272B; P [64][64] bf16 stride 144B.
#define AQH 0
#define AQL 17408
#define AKH 34816
#define AKL 52224
#define AVH 69632
#define AVL 87040
#define APH 104448
#define APL 113664
#define AREDM 122880
#define AREDL 123392
#define AMROW 123904
#define ALROW 124160
#define AAROW 124416
#define ATTN_SMEM 124672

__global__ void __launch_bounds__(256) attn_tc_kernel(){
    extern __shared__ __align__(16) char smem[];
    uint32_t sb = smem_u32(smem);
    float* redm = (float*)(smem + AREDM);
    float* redl = (float*)(smem + AREDL);
    float* mrow = (float*)(smem + AMROW);
    float* lrow = (float*)(smem + ALROW);
    float* arow = (float*)(smem + AAROW);

    int b = blockIdx.y, qt = blockIdx.x;
    int tid = threadIdx.x, lane = tid&31, wid = tid>>5;
    int wr = wid>>1, wc = wid&1;
    long qbase = (long)b*NT + (long)qt*64;
    const float scale = 0.0883883476483184f;

    int lr = tid>>2, cb = (tid&3)*32;   // load mapping: row, col-base (32 cols/thread)
    int ldst = lr*272 + cb*2;

    // load + split Q (scaled)
    {
        const float* qs = g_q + (qbase+lr)*NH + cb;
        #pragma unroll
        for(int q=0;q<8;q++){
            float4 v = *(const float4*)(qs + q*4);
            uint32_t h0,l0,h1,l1;
            split_pair(v.x*scale, v.y*scale, h0,l0);
            split_pair(v.z*scale, v.w*scale, h1,l1);
            *(uint2*)(smem + AQH + ldst + q*8) = make_uint2(h0,h1);
            *(uint2*)(smem + AQL + ldst + q*8) = make_uint2(l0,l1);
        }
    }
    if(tid<64){ mrow[tid]=-INFINITY; lrow[tid]=0.f; }

    float oacc[8][4];
    #pragma unroll
    for(int nf=0;nf<8;nf++)
        #pragma unroll
        for(int u=0;u<4;u++) oacc[nf][u]=0.f;

    int r0 = wr*16 + (lane>>2), r1 = r0+8;

    // ldmatrix addresses
    int mid = lane>>3, l7 = lane&7;
    uint32_t qAddr, pAddr, kAddr[2], vAddr[4];
    {
        int row = wr*16 + (mid&1)*8 + l7;
        qAddr = sb + AQH + row*272 + (mid>>1)*16;
        pAddr = sb + APH + row*144 + (mid>>1)*16;
        #pragma unroll
        for(int g=0;g<2;g++){
            int n = wc*32 + g*16 + (mid>>1)*8 + l7;
            kAddr[g] = sb + AKH + n*272 + (mid&1)*16;
        }
        #pragma unroll
        for(int g=0;g<4;g++){
            int krow = (mid&1)*8 + l7;
            int ncol = wc*64 + g*16 + (mid>>1)*8;
            vAddr[g] = sb + AVH + krow*272 + ncol*2;
        }
    }
    __syncthreads();

    for(int kt=0; kt<NT/64; kt++){
        long kbase = (long)b*NT + (long)kt*64;
        // load + split K and V tiles
        {
            const float* ks = g_k + (kbase+lr)*NH + cb;
            const float* vs = g_v + (kbase+lr)*NH + cb;
            #pragma unroll
            for(int q=0;q<8;q++){
                float4 v = *(const float4*)(ks + q*4);
                uint32_t h0,l0,h1,l1;
                split_pair(v.x,v.y,h0,l0);
                split_pair(v.z,v.w,h1,l1);
                *(uint2*)(smem + AKH + ldst + q*8) = make_uint2(h0,h1);
                *(uint2*)(smem + AKL + ldst + q*8) = make_uint2(l0,l1);
            }
            #pragma unroll
            for(int q=0;q<8;q++){
                float4 v = *(const float4*)(vs + q*4);
                uint32_t h0,l0,h1,l1;
                split_pair(v.x,v.y,h0,l0);
                split_pair(v.z,v.w,h1,l1);
                *(uint2*)(smem + AVH + ldst + q*8) = make_uint2(h0,h1);
                *(uint2*)(smem + AVL + ldst + q*8) = make_uint2(l0,l1);
            }
        }
        __syncthreads();

        // ---- S = Q K^T (3xBF16) ----
        float sacc[4][4];
        #pragma unroll
        for(int nf=0;nf<4;nf++)
            #pragma unroll
            for(int u=0;u<4;u++) sacc[nf][u]=0.f;

        #pragma unroll
        for(int s=0;s<8;s++){
            uint32_t qh[4], ql[4];
            LDM4(qh[0],qh[1],qh[2],qh[3], qAddr + s*32);
            LDM4(ql[0],ql[1],ql[2],ql[3], qAddr + (AQL-AQH) + s*32);
            #pragma unroll
            for(int g=0;g<2;g++){
                uint32_t kh[4], kl[4];
                LDM4(kh[0],kh[1],kh[2],kh[3], kAddr[g] + s*32);
                LDM4(kl[0],kl[1],kl[2],kl[3], kAddr[g] + (AKL-AKH) + s*32);
                #pragma unroll
                for(int sub=0;sub<2;sub++){
                    float* C = sacc[g*2+sub];
                    mma16(C, qh[0],qh[1],qh[2],qh[3], kh[sub*2],kh[sub*2+1]);
                    mma16(C, qh[0],qh[1],qh[2],qh[3], kl[sub*2],kl[sub*2+1]);
                    mma16(C, ql[0],ql[1],ql[2],ql[3], kh[sub*2],kh[sub*2+1]);
                }
            }
        }

        // ---- row max ----
        float pm0 = fmaxf(fmaxf(sacc[0][0],sacc[0][1]), fmaxf(sacc[1][0],sacc[1][1]));
        pm0 = fmaxf(pm0, fmaxf(fmaxf(sacc[2][0],sacc[2][1]), fmaxf(sacc[3][0],sacc[3][1])));
        float pm1 = fmaxf(fmaxf(sacc[0][2],sacc[0][3]), fmaxf(sacc[1][2],sacc[1][3]));
        pm1 = fmaxf(pm1, fmaxf(fmaxf(sacc[2][2],sacc[2][3]), fmaxf(sacc[3][2],sacc[3][3])));
        pm0 = fmaxf(pm0, __shfl_xor_sync(0xffffffffu, pm0, 1));
        pm0 = fmaxf(pm0, __shfl_xor_sync(0xffffffffu, pm0, 2));
        pm1 = fmaxf(pm1, __shfl_xor_sync(0xffffffffu, pm1, 1));
        pm1 = fmaxf(pm1, __shfl_xor_sync(0xffffffffu, pm1, 2));
        if((lane&3)==0){
            redm[wc*64 + r0] = pm0;
            redm[wc*64 + r1] = pm1;
        }
        __syncthreads();
        if(tid<64){
            float mo = mrow[tid];
            float mn = fmaxf(mo, fmaxf(redm[tid], redm[64+tid]));
            arow[tid] = expf(mo - mn);
            mrow[tid] = mn;
        }
        __syncthreads();

        // ---- P = exp(S-m) -> split bf16 smem; partial sums; rescale oacc ----
        float mn0 = mrow[r0], mn1 = mrow[r1];
        float a0 = arow[r0], a1 = arow[r1];
        float rs0=0.f, rs1=0.f;
        #pragma unroll
        for(int nf=0;nf<4;nf++){
            int col = wc*32 + nf*8 + (lane&3)*2;
            float p0 = expf(sacc[nf][0]-mn0);
            float p1 = expf(sacc[nf][1]-mn0);
            float p2 = expf(sacc[nf][2]-mn1);
            float p3 = expf(sacc[nf][3]-mn1);
            rs0 += p0+p1; rs1 += p2+p3;
            uint32_t hi,lo;
            split_pair(p0,p1,hi,lo);
            *(uint32_t*)(smem + APH + r0*144 + col*2) = hi;
            *(uint32_t*)(smem + APL + r0*144 + col*2) = lo;
            split_pair(p2,p3,hi,lo);
            *(uint32_t*)(smem + APH + r1*144 + col*2) = hi;
            *(uint32_t*)(smem + APL + r1*144 + col*2) = lo;
        }
        rs0 += __shfl_xor_sync(0xffffffffu, rs0, 1);
        rs0 += __shfl_xor_sync(0xffffffffu, rs0, 2);
        rs1 += __shfl_xor_sync(0xffffffffu, rs1, 1);
        rs1 += __shfl_xor_sync(0xffffffffu, rs1, 2);
        if((lane&3)==0){
            redl[wc*64 + r0] = rs0;
            redl[wc*64 + r1] = rs1;
        }
        #pragma unroll
        for(int nf=0;nf<8;nf++){
            oacc[nf][0]*=a0; oacc[nf][1]*=a0;
            oacc[nf][2]*=a1; oacc[nf][3]*=a1;
        }
        __syncthreads();
        if(tid<64) lrow[tid] = lrow[tid]*arow[tid] + redl[tid] + redl[64+tid];

        // ---- O += P V (3xBF16) ----
        #pragma unroll
        for(int s=0;s<4;s++){
            uint32_t ph[4], pl[4];
            LDM4(ph[0],ph[1],ph[2],ph[3], pAddr + s*32);
            LDM4(pl[0],pl[1],pl[2],pl[3], pAddr + (APL-APH) + s*32);
            #pragma unroll
            for(int g=0;g<4;g++){
                uint32_t vh[4], vl[4];
                LDM4T(vh[0],vh[1],vh[2],vh[3], vAddr[g] + s*4352);
                LDM4T(vl[0],vl[1],vl[2],vl[3], vAddr[g] + (AVL-AVH) + s*4352);
                #pragma unroll
                for(int sub=0;sub<2;sub++){
                    float* C = oacc[g*2+sub];
                    mma16(C, ph[0],ph[1],ph[2],ph[3], vh[sub*2],vh[sub*2+1]);
                    mma16(C, ph[0],ph[1],ph[2],ph[3], vl[sub*2],vl[sub*2+1]);
                    mma16(C, pl[0],pl[1],pl[2],pl[3], vh[sub*2],vh[sub*2+1]);
                }
            }
        }
        __syncthreads();
    }

    // ---- epilogue: normalize + store ----
    float il0 = 1.f/lrow[r0], il1 = 1.f/lrow[r1];
    #pragma unroll
    for(int nf=0;nf<8;nf++){
        int col = wc*64 + nf*8 + (lane&3)*2;
        g_o[(qbase+r0)*NH + col    ] = oacc[nf][0]*il0;
        g_o[(qbase+r0)*NH + col + 1] = oacc[nf][1]*il0;
        g_o[(qbase+r1)*NH + col    ] = oacc[nf][2]*il1;
        g_o[(qbase+r1)*NH + col + 1] = oacc[nf][3]*il1;
    }
}

// ---------------------------------------------------------------------------
extern "C" void kernel_launch(void* const* d_in, const int* in_sizes, int n_in,
                              void* d_out, int out_size){
    (void)in_sizes; (void)n_in; (void)out_size;
    const float* hs   = (const float*)d_in[0];
    const float* sim  = (const float*)d_in[1];
    const float* gates= (const float*)d_in[2];
    const float* qp   = (const float*)d_in[3];
    const float* kp   = (const float*)d_in[4];
    const float* vp   = (const float*)d_in[5];
    const float* op   = (const float*)d_in[6];
    float* out = (float*)d_out;

    cudaFuncSetAttribute(attn_tc_kernel, cudaFuncAttributeMaxDynamicSharedMemorySize, ATTN_SMEM);
    cudaFuncSetAttribute(bf16_gemm_kernel<NC,NC,NH,NH,1>, cudaFuncAttributeMaxDynamicSharedMemorySize, GS_TOTAL);
    cudaFuncSetAttribute(bf16_gemm_kernel<NH,NH,NC,NC,0>, cudaFuncAttributeMaxDynamicSharedMemorySize, GS_TOTAL);

    zero_kernel<<<2048,256>>>(out);
    prep_kernel<<<NE,256>>>(sim,gates);
    gate_kernel<<<NN,128>>>(hs);
    scan_kernel<<<1,32>>>();
    pairfill_kernel<<<NN/256,256>>>();
    bf16_gemm_kernel<NC,NC,NH,NH,1><<<dim3(64,3,16),256,GS_TOTAL>>>(hs,qp,kp,vp,nullptr);
    attn_tc_kernel<<<dim3(NT/64,NB),256,ATTN_SMEM>>>();
    bf16_gemm_kernel<NH,NH,NC,NC,0><<<dim3(64,8,16),256,GS_TOTAL>>>(nullptr,op,nullptr,nullptr,out);
}

// round 8
// speedup vs baseline: 2.7209x; 1.0707x over previous
#include <cuda_runtime.h>
#include <cuda_bf16.h>
#include <math.h>
#include <cstdint>

#define NB 4
#define NT 2048
#define NC 1024
#define NH 128
#define NE 16
#define NN (NB*NT)   // 8192 tokens

// ---------------- scratch (static device allocations; no runtime alloc) ----
static __device__ float g_sn[NC*NE];
static __device__ float g_sig[NE];
static __device__ int   g_nact[NN];
static __device__ unsigned char g_tok_e[NN*NE];
static __device__ float g_tok_w[NN*NE];
static __device__ int   g_cnt[NE];
static __device__ int   g_off[NE];
static __device__ int   g_cur[NE];
static __device__ int   g_pair_tok[NN*NE];
static __device__ float g_pair_w[NN*NE];
static __device__ float g_q[NN*NH];
static __device__ float g_k[NN*NH];
static __device__ float g_v[NN*NH];

// packed bf16x2 hi/lo operand arrays
static __device__ uint32_t g_xh[NN*NC/2],  g_xl[NN*NC/2];        // hidden states
static __device__ uint32_t g_wh[3*NE*NC*NH/2], g_wl[3*NE*NC*NH/2]; // q/k/v proj
static __device__ uint32_t g_oph[NE*NH*NC/2], g_opl[NE*NH*NC/2];   // o proj
static __device__ uint32_t g_qh[NN*NH/2], g_ql[NN*NH/2];
static __device__ uint32_t g_kh[NN*NH/2], g_kl[NN*NH/2];
static __device__ uint32_t g_vh[NN*NH/2], g_vl[NN*NH/2];
static __device__ uint32_t g_oh[NN*NH/2], g_ol[NN*NH/2];         // attn output

// ================= helpers ==================================================
__device__ __forceinline__ uint32_t smem_u32(const void* p){
    uint32_t a;
    asm("{ .reg .u64 t; cvta.to.shared.u64 t, %1; cvt.u32.u64 %0, t; }" : "=r"(a) : "l"(p));
    return a;
}
__device__ __forceinline__ void split_pair(float x, float y, uint32_t& hi, uint32_t& lo){
    __nv_bfloat162 h = __floats2bfloat162_rn(x, y);
    float rx = x - __low2float(h);
    float ry = y - __high2float(h);
    __nv_bfloat162 l = __floats2bfloat162_rn(rx, ry);
    hi = *(uint32_t*)&h;
    lo = *(uint32_t*)&l;
}
#define CP16(dst,src) asm volatile("cp.async.ca.shared.global [%0], [%1], 16;" :: "r"(dst), "l"(src))
#define CP_COMMIT()   asm volatile("cp.async.commit_group;" ::: "memory")
#define CP_WAIT(n)    asm volatile("cp.async.wait_group %0;" :: "n"(n) : "memory")
#define LDM4(r0,r1,r2,r3,addr) \
    asm volatile("ldmatrix.sync.aligned.m8n8.x4.shared.b16 {%0,%1,%2,%3}, [%4];" \
        : "=r"(r0),"=r"(r1),"=r"(r2),"=r"(r3) : "r"(addr))
#define LDM4T(r0,r1,r2,r3,addr) \
    asm volatile("ldmatrix.sync.aligned.m8n8.x4.trans.shared.b16 {%0,%1,%2,%3}, [%4];" \
        : "=r"(r0),"=r"(r1),"=r"(r2),"=r"(r3) : "r"(addr))
__device__ __forceinline__ void mma16(float c[4],
        uint32_t a0,uint32_t a1,uint32_t a2,uint32_t a3,
        uint32_t b0,uint32_t b1){
    asm volatile("mma.sync.aligned.m16n8k16.row.col.f32.bf16.bf16.f32 "
        "{%0,%1,%2,%3}, {%4,%5,%6,%7}, {%8,%9}, {%0,%1,%2,%3};"
        : "+f"(c[0]),"+f"(c[1]),"+f"(c[2]),"+f"(c[3])
        : "r"(a0),"r"(a1),"r"(a2),"r"(a3),"r"(b0),"r"(b1));
}

// ---------------- zero / init ----------------
__global__ void zero_kernel(float* __restrict__ out){
    long i = (long)blockIdx.x*blockDim.x + threadIdx.x;
    long stride = (long)gridDim.x*blockDim.x;
    for(long j=i;j<(long)NN*NH;j+=stride){ g_q[j]=0.f; g_k[j]=0.f; g_v[j]=0.f; }
    for(long j=i;j<(long)NN*NC;j+=stride) out[j]=0.f;
    if(i<NE) g_cnt[(int)i]=0;
}

// ---------------- sim-matrix column normalization + sigmoid(gates) ---------
__global__ void prep_kernel(const float* __restrict__ sim, const float* __restrict__ gates){
    int e = blockIdx.x;
    __shared__ float red[256];
    float ss=0.f;
    for(int c=threadIdx.x;c<NC;c+=256){ float v=sim[c*NE+e]; ss+=v*v; }
    red[threadIdx.x]=ss; __syncthreads();
    for(int s=128;s>0;s>>=1){ if(threadIdx.x<s) red[threadIdx.x]+=red[threadIdx.x+s]; __syncthreads(); }
    float inv = 1.f/fmaxf(sqrtf(red[0]),1e-12f);
    for(int c=threadIdx.x;c<NC;c+=256) g_sn[c*NE+e]=sim[c*NE+e]*inv;
    if(threadIdx.x==0) g_sig[e]=1.f/(1.f+expf(-gates[e]));
}

// ---------------- weight pre-pack (qkv proj + o proj) ----------------------
__global__ void conv_w_kernel(const float* __restrict__ qp, const float* __restrict__ kp,
                              const float* __restrict__ vp, const float* __restrict__ op){
    const long NW_QKV = (long)3*NE*NC*NH/2;
    const long NW_OP  = (long)NE*NH*NC/2;
    const long PERP   = (long)NE*NC*NH/2;
    long stride = (long)gridDim.x*blockDim.x;
    for(long idx = (long)blockIdx.x*blockDim.x + threadIdx.x; idx < NW_QKV+NW_OP; idx += stride){
        uint32_t hi,lo;
        if(idx < NW_QKV){
            long p = idx / PERP;
            long r = idx - p*PERP;
            const float* src = (p==0? qp : (p==1? kp : vp)) + r*2;
            float2 v = *(const float2*)src;
            split_pair(v.x,v.y,hi,lo);
            g_wh[idx]=hi; g_wl[idx]=lo;
        } else {
            long r = idx - NW_QKV;
            float2 v = *(const float2*)(op + r*2);
            split_pair(v.x,v.y,hi,lo);
            g_oph[r]=hi; g_opl[r]=lo;
        }
    }
}

// ---------------- gating (fused with X bf16 hi/lo pack) --------------------
__global__ void __launch_bounds__(128) gate_kernel(const float* __restrict__ X){
    int n = blockIdx.x;
    const float2* x2 = (const float2*)(X + (long)n*NC);
    int tid = threadIdx.x;
    float ssq=0.f, dot[NE];
    #pragma unroll
    for(int e=0;e<NE;e++) dot[e]=0.f;
    for(int j=tid;j<NC/2;j+=128){
        float2 xv = x2[j];
        uint32_t hi,lo; split_pair(xv.x,xv.y,hi,lo);
        g_xh[(long)n*(NC/2)+j]=hi;
        g_xl[(long)n*(NC/2)+j]=lo;
        ssq += xv.x*xv.x + xv.y*xv.y;
        const float4* sr0 = (const float4*)(g_sn + (2*j)*NE);
        const float4* sr1 = (const float4*)(g_sn + (2*j+1)*NE);
        #pragma unroll
        for(int q=0;q<4;q++){
            float4 a = sr0[q], b = sr1[q];
            dot[q*4+0]+=xv.x*a.x+xv.y*b.x; dot[q*4+1]+=xv.x*a.y+xv.y*b.y;
            dot[q*4+2]+=xv.x*a.z+xv.y*b.z; dot[q*4+3]+=xv.x*a.w+xv.y*b.w;
        }
    }
    #pragma unroll
    for(int off=16;off>0;off>>=1){
        ssq += __shfl_down_sync(0xffffffffu, ssq, off);
        #pragma unroll
        for(int e=0;e<NE;e++) dot[e]+=__shfl_down_sync(0xffffffffu, dot[e], off);
    }
    __shared__ float part[4][NE+1];
    int w = tid>>5, lane = tid&31;
    if(lane==0){ part[w][0]=ssq; for(int e=0;e<NE;e++) part[w][e+1]=dot[e]; }
    __syncthreads();
    if(tid==0){
        float S = part[0][0]+part[1][0]+part[2][0]+part[3][0];
        float inv = 1.f/fmaxf(sqrtf(S),1e-12f);
        float logit[NE];
        #pragma unroll
        for(int e=0;e<NE;e++){
            float d = part[0][e+1]+part[1][e+1]+part[2][e+1]+part[3][e+1];
            logit[e] = d*inv - g_sig[e];
        }
        int act[NE]; int na=0;
        for(int e=0;e<NE;e++) if(logit[e]>0.f) act[na++]=e;
        if(na==0){
            int i1=0;
            for(int e=1;e<NE;e++) if(logit[e]>logit[i1]) i1=e;
            int i2=-1;
            for(int e=0;e<NE;e++) if(e!=i1 && (i2<0 || logit[e]>logit[i2])) i2=e;
            int a = i1<i2? i1:i2; int b2 = i1<i2? i2:i1;
            act[0]=a; act[1]=b2; na=2;
        }
        float vals[NE]; float mx=-1e30f;
        for(int k=0;k<na;k++){ vals[k]=fmaxf(logit[act[k]],0.f); mx=fmaxf(mx,vals[k]); }
        float sum=0.f;
        for(int k=0;k<na;k++){ vals[k]=expf(vals[k]-mx); sum+=vals[k]; }
        float isum = 1.f/sum;
        g_nact[n]=na;
        for(int k=0;k<na;k++){
            g_tok_e[n*NE+k]=(unsigned char)act[k];
            g_tok_w[n*NE+k]=vals[k]*isum;
            atomicAdd(&g_cnt[act[k]],1);
        }
    }
}

__global__ void scan_kernel(){
    if(threadIdx.x==0){
        int o=0;
        for(int e=0;e<NE;e++){ g_off[e]=o; o+=g_cnt[e]; }
    }
    if(threadIdx.x<NE) g_cur[threadIdx.x]=0;
}

__global__ void pairfill_kernel(){
    int n = blockIdx.x*blockDim.x + threadIdx.x;
    if(n>=NN) return;
    int na=g_nact[n];
    for(int k=0;k<na;k++){
        int e=g_tok_e[n*NE+k];
        int s=atomicAdd(&g_cur[e],1);
        int p=g_off[e]+s;
        g_pair_tok[p]=n;
        g_pair_w[p]=g_tok_w[n*NE+k];
    }
}

// ---------------- q/k/v fp32 -> packed bf16 hi/lo (Q pre-scaled) -----------
__global__ void conv_qkv_kernel(){
    const float scale = 0.0883883476483184f;  // 1/sqrt(128)
    long idx = (long)blockIdx.x*blockDim.x + threadIdx.x;  // word index < NN*NH/2
    if(idx >= (long)NN*NH/2) return;
    uint32_t hi,lo;
    float2 q = *(const float2*)(g_q + idx*2);
    split_pair(q.x*scale, q.y*scale, hi, lo);
    g_qh[idx]=hi; g_ql[idx]=lo;
    float2 k = *(const float2*)(g_k + idx*2);
    split_pair(k.x, k.y, hi, lo);
    g_kh[idx]=hi; g_kl[idx]=lo;
    float2 v = *(const float2*)(g_v + idx*2);
    split_pair(v.x, v.y, hi, lo);
    g_vh[idx]=hi; g_vl[idx]=lo;
}

// =============== 3xBF16 m16n8k16 grouped GEMM, cp.async pipelined ==========
// CTA: 128 gathered rows x 128 out cols, 8 warps (warp tile 64x32), k-chunks 32.
// A smem rows: 32 bf16 (64B) stride 80B. B smem k-rows: 128 bf16 (256B) stride 272B.
// 2-stage double buffer, hi+lo per stage.
#define GS_TOK 0
#define GS_W   512
#define GS_A   1024
#define GS_ABUF 10240
#define GS_B   (GS_A + 4*GS_ABUF)      // 41984
#define GS_BBUF 8704
#define GS_TOTAL (GS_B + 4*GS_BBUF)    // 76800

template<int KTOT, int LDAW, int LDBW, int LDO, int QKV>
__global__ void __launch_bounds__(256) bf16_gemm_kernel(float* __restrict__ OutP){
    int e = blockIdx.z;
    int cnt = g_cnt[e];
    int m0 = blockIdx.x*128;
    if(m0>=cnt) return;
    int off = g_off[e];

    const uint32_t *Axh, *Axl, *Bh, *Bl;
    float* Out; int n0;
    if(QKV){
        Axh = g_xh; Axl = g_xl;
        long woff = ((long)blockIdx.y*NE + e)*NC*(NH/2);
        Bh = g_wh + woff; Bl = g_wl + woff;
        Out = (blockIdx.y==0)? g_q : (blockIdx.y==1? g_k : g_v);
        n0 = 0;
    } else {
        Axh = g_oh; Axl = g_ol;
        long woff = (long)e*NH*(NC/2);
        Bh = g_oph + woff; Bl = g_opl + woff;
        Out = OutP;
        n0 = blockIdx.y*128;
    }
    int n0w = n0/2;

    extern __shared__ __align__(16) char smem[];
    uint32_t sb = smem_u32(smem);
    int*   stok = (int*)(smem + GS_TOK);
    float* sw   = (float*)(smem + GS_W);

    int tid=threadIdx.x, lane=tid&31, wid=tid>>5;
    int wr = wid>>2, wc = wid&3;

    if(tid<128){
        int m=m0+tid; int mm = m<cnt? m : cnt-1;
        stok[tid]=g_pair_tok[off+mm];
        sw[tid]= (m<cnt)? g_pair_w[off+mm] : 0.f;
    }
    __syncthreads();

    // prefetch assignments
    int ar = tid>>1, ahalf = tid&1;                 // A: 2 thr/row, 32B each (8 words)
    const uint32_t* ash = Axh + (long)stok[ar]*LDAW + ahalf*8;
    const uint32_t* asl = Axl + (long)stok[ar]*LDAW + ahalf*8;
    uint32_t adst = sb + GS_A + ar*80 + ahalf*32;
    int bk = tid>>3, bn = (tid&7)*8;                // B: 8 thr/row, 32B each
    const uint32_t* bsh = Bh + (long)bk*LDBW + n0w + bn;
    const uint32_t* bsl = Bl + (long)bk*LDBW + n0w + bn;
    uint32_t bdst = sb + GS_B + bk*272 + bn*4;

    const int NCH = KTOT/32;

    // ldmatrix addresses (stage-relative)
    int mid = lane>>3, l7 = lane&7;
    uint32_t aRel[4];
    #pragma unroll
    for(int mf=0;mf<4;mf++){
        int row = wr*64 + mf*16 + (mid&1)*8 + l7;
        aRel[mf] = row*80 + (mid>>1)*16;
    }
    uint32_t bRel[2];
    #pragma unroll
    for(int g=0;g<2;g++){
        int krow = (mid&1)*8 + l7;
        int ncol = wc*32 + g*16 + (mid>>1)*8;
        bRel[g] = krow*272 + ncol*2;
    }

    float acc[4][4][4];
    #pragma unroll
    for(int mf=0;mf<4;mf++)
        #pragma unroll
        for(int nf=0;nf<4;nf++)
            #pragma unroll
            for(int u=0;u<4;u++) acc[mf][nf][u]=0.f;

    // prefetch chunk 0
    {
        CP16(adst,               ash);
        CP16(adst+16,            ash+4);
        CP16(adst+GS_ABUF,       asl);
        CP16(adst+GS_ABUF+16,    asl+4);
        CP16(bdst,               bsh);
        CP16(bdst+16,            bsh+4);
        CP16(bdst+GS_BBUF,       bsl);
        CP16(bdst+GS_BBUF+16,    bsl+4);
        CP_COMMIT();
    }

    for(int c=0;c<NCH;c++){
        if(c+1<NCH){
            int st = (c+1)&1;
            uint32_t ad = adst + st*(2*GS_ABUF);
            uint32_t bd = bdst + st*(2*GS_BBUF);
            const uint32_t* ash2 = ash + (c+1)*16;
            const uint32_t* asl2 = asl + (c+1)*16;
            const uint32_t* bsh2 = bsh + (long)(c+1)*32*LDBW;
            const uint32_t* bsl2 = bsl + (long)(c+1)*32*LDBW;
            CP16(ad,            ash2);
            CP16(ad+16,         ash2+4);
            CP16(ad+GS_ABUF,    asl2);
            CP16(ad+GS_ABUF+16, asl2+4);
            CP16(bd,            bsh2);
            CP16(bd+16,         bsh2+4);
            CP16(bd+GS_BBUF,    bsl2);
            CP16(bd+GS_BBUF+16, bsl2+4);
            CP_COMMIT();
            CP_WAIT(1);
        } else {
            CP_WAIT(0);
        }
        __syncthreads();

        uint32_t stA = sb + GS_A + (c&1)*(2*GS_ABUF);
        uint32_t stB = sb + GS_B + (c&1)*(2*GS_BBUF);

        #pragma unroll
        for(int s=0;s<2;s++){
            uint32_t ahh[4][4], alo[4][4];
            #pragma unroll
            for(int mf=0;mf<4;mf++){
                LDM4(ahh[mf][0],ahh[mf][1],ahh[mf][2],ahh[mf][3], stA + aRel[mf] + s*32);
                LDM4(alo[mf][0],alo[mf][1],alo[mf][2],alo[mf][3], stA + GS_ABUF + aRel[mf] + s*32);
            }
            #pragma unroll
            for(int g=0;g<2;g++){
                uint32_t bh[4], bl[4];
                LDM4T(bh[0],bh[1],bh[2],bh[3], stB + bRel[g] + s*4352);
                LDM4T(bl[0],bl[1],bl[2],bl[3], stB + GS_BBUF + bRel[g] + s*4352);
                #pragma unroll
                for(int sub=0;sub<2;sub++){
                    #pragma unroll
                    for(int mf=0;mf<4;mf++){
                        float* C = acc[mf][g*2+sub];
                        mma16(C, ahh[mf][0],ahh[mf][1],ahh[mf][2],ahh[mf][3], bh[sub*2],bh[sub*2+1]);
                        mma16(C, ahh[mf][0],ahh[mf][1],ahh[mf][2],ahh[mf][3], bl[sub*2],bl[sub*2+1]);
                        mma16(C, alo[mf][0],alo[mf][1],alo[mf][2],alo[mf][3], bh[sub*2],bh[sub*2+1]);
                    }
                }
            }
        }
        __syncthreads();
    }

    // epilogue: weight-scale + atomic scatter
    #pragma unroll
    for(int mf=0;mf<4;mf++){
        int r0 = wr*64 + mf*16 + (lane>>2);
        int r1 = r0 + 8;
        float w0 = sw[r0], w1 = sw[r1];
        int live0 = (m0 + r0 < cnt), live1 = (m0 + r1 < cnt);
        long b0 = (long)stok[r0]*LDO + n0;
        long b1 = (long)stok[r1]*LDO + n0;
        #pragma unroll
        for(int nf=0;nf<4;nf++){
            int col = wc*32 + nf*8 + (lane&3)*2;
            if(live0){
                atomicAdd(&Out[b0 + col    ], acc[mf][nf][0]*w0);
                atomicAdd(&Out[b0 + col + 1], acc[mf][nf][1]*w0);
            }
            if(live1){
                atomicAdd(&Out[b1 + col    ], acc[mf][nf][2]*w1);
                atomicAdd(&Out[b1 + col + 1], acc[mf][nf][3]*w1);
            }
        }
    }
}

// ------------- flash attention, 3xBF16 mma + ldmatrix + cp.async -----------
// CTA 64 q rows, 8 warps: wr=wid>>1 (m16 tile), wc=wid&1 (n half).
// Q/K/V smem rows 272B stride; P rows 144B. KV double-buffered (hi+lo each).
#define AQH 0
#define AQL 17408
#define AKV0 34816
#define AKV1 104448
#define AKVST 17408            // sub-buffer size: Kh,Kl,Vh,Vl
#define APH 174080
#define APL 183296
#define AREDM 192512
#define AREDL 193024
#define AMROW 193536
#define ALROW 193792
#define AAROW 194048
#define ATTN_SMEM 194304

__global__ void __launch_bounds__(256) attn_tc_kernel(){
    extern __shared__ __align__(16) char smem[];
    uint32_t sb = smem_u32(smem);
    float* redm = (float*)(smem + AREDM);
    float* redl = (float*)(smem + AREDL);
    float* mrow = (float*)(smem + AMROW);
    float* lrow = (float*)(smem + ALROW);
    float* arow = (float*)(smem + AAROW);

    int b = blockIdx.y, qt = blockIdx.x;
    int tid = threadIdx.x, lane = tid&31, wid = tid>>5;
    int wr = wid>>1, wc = wid&1;
    long qbase = (long)b*NT + (long)qt*64;

    int lr = tid>>2, lq = tid&3;        // 4 thr/row, 64B (16 words) each
    uint32_t ldst = lr*272 + lq*64;

    // prologue: prefetch Q (pre-scaled) + KV tile 0, one group
    {
        const uint32_t* qh = g_qh + (qbase+lr)*64 + lq*16;
        const uint32_t* ql = g_ql + (qbase+lr)*64 + lq*16;
        #pragma unroll
        for(int q=0;q<4;q++){
            CP16(sb + AQH + ldst + q*16, qh + q*4);
            CP16(sb + AQL + ldst + q*16, ql + q*4);
        }
        long kb = (long)b*NT;           // kt = 0
        const uint32_t* kh = g_kh + (kb+lr)*64 + lq*16;
        const uint32_t* kl = g_kl + (kb+lr)*64 + lq*16;
        const uint32_t* vh = g_vh + (kb+lr)*64 + lq*16;
        const uint32_t* vl = g_vl + (kb+lr)*64 + lq*16;
        #pragma unroll
        for(int q=0;q<4;q++){
            CP16(sb + AKV0 + 0*AKVST + ldst + q*16, kh + q*4);
            CP16(sb + AKV0 + 1*AKVST + ldst + q*16, kl + q*4);
            CP16(sb + AKV0 + 2*AKVST + ldst + q*16, vh + q*4);
            CP16(sb + AKV0 + 3*AKVST + ldst + q*16, vl + q*4);
        }
        CP_COMMIT();
    }
    if(tid<64){ mrow[tid]=-INFINITY; lrow[tid]=0.f; }

    float oacc[8][4];
    #pragma unroll
    for(int nf=0;nf<8;nf++)
        #pragma unroll
        for(int u=0;u<4;u++) oacc[nf][u]=0.f;

    int r0 = wr*16 + (lane>>2), r1 = r0+8;

    // ldmatrix relative addresses
    int mid = lane>>3, l7 = lane&7;
    uint32_t qAddr, pAddr, kRel[2], vRel[4];
    {
        int row = wr*16 + (mid&1)*8 + l7;
        qAddr = sb + AQH + row*272 + (mid>>1)*16;
        pAddr = sb + APH + row*144 + (mid>>1)*16;
        #pragma unroll
        for(int g=0;g<2;g++){
            int n = wc*32 + g*16 + (mid>>1)*8 + l7;
            kRel[g] = n*272 + (mid&1)*16;
        }
        #pragma unroll
        for(int g=0;g<4;g++){
            int krow = (mid&1)*8 + l7;
            int ncol = wc*64 + g*16 + (mid>>1)*8;
            vRel[g] = krow*272 + ncol*2;
        }
    }

    for(int kt=0; kt<NT/64; kt++){
        if(kt+1 < NT/64){
            uint32_t base = sb + (((kt+1)&1) ? AKV1 : AKV0);
            long kb = (long)b*NT + (long)(kt+1)*64;
            const uint32_t* kh = g_kh + (kb+lr)*64 + lq*16;
            const uint32_t* kl = g_kl + (kb+lr)*64 + lq*16;
            const uint32_t* vh = g_vh + (kb+lr)*64 + lq*16;
            const uint32_t* vl = g_vl + (kb+lr)*64 + lq*16;
            #pragma unroll
            for(int q=0;q<4;q++){
                CP16(base + 0*AKVST + ldst + q*16, kh + q*4);
                CP16(base + 1*AKVST + ldst + q*16, kl + q*4);
                CP16(base + 2*AKVST + ldst + q*16, vh + q*4);
                CP16(base + 3*AKVST + ldst + q*16, vl + q*4);
            }
            CP_COMMIT();
            CP_WAIT(1);
        } else {
            CP_WAIT(0);
        }
        __syncthreads();

        uint32_t kvb = sb + ((kt&1) ? AKV1 : AKV0);
        uint32_t kH = kvb, kL = kvb + AKVST, vH = kvb + 2*AKVST, vL = kvb + 3*AKVST;

        // ---- S = Q K^T (3xBF16) ----
        float sacc[4][4];
        #pragma unroll
        for(int nf=0;nf<4;nf++)
            #pragma unroll
            for(int u=0;u<4;u++) sacc[nf][u]=0.f;

        #pragma unroll
        for(int s=0;s<8;s++){
            uint32_t qh[4], ql[4];
            LDM4(qh[0],qh[1],qh[2],qh[3], qAddr + s*32);
            LDM4(ql[0],ql[1],ql[2],ql[3], qAddr + (AQL-AQH) + s*32);
            #pragma unroll
            for(int g=0;g<2;g++){
                uint32_t khf[4], klf[4];
                LDM4(khf[0],khf[1],khf[2],khf[3], kH + kRel[g] + s*32);
                LDM4(klf[0],klf[1],klf[2],klf[3], kL + kRel[g] + s*32);
                #pragma unroll
                for(int sub=0;sub<2;sub++){
                    float* C = sacc[g*2+sub];
                    mma16(C, qh[0],qh[1],qh[2],qh[3], khf[sub*2],khf[sub*2+1]);
                    mma16(C, qh[0],qh[1],qh[2],qh[3], klf[sub*2],klf[sub*2+1]);
                    mma16(C, ql[0],ql[1],ql[2],ql[3], khf[sub*2],khf[sub*2+1]);
                }
            }
        }

        // ---- row max ----
        float pm0 = fmaxf(fmaxf(sacc[0][0],sacc[0][1]), fmaxf(sacc[1][0],sacc[1][1]));
        pm0 = fmaxf(pm0, fmaxf(fmaxf(sacc[2][0],sacc[2][1]), fmaxf(sacc[3][0],sacc[3][1])));
        float pm1 = fmaxf(fmaxf(sacc[0][2],sacc[0][3]), fmaxf(sacc[1][2],sacc[1][3]));
        pm1 = fmaxf(pm1, fmaxf(fmaxf(sacc[2][2],sacc[2][3]), fmaxf(sacc[3][2],sacc[3][3])));
        pm0 = fmaxf(pm0, __shfl_xor_sync(0xffffffffu, pm0, 1));
        pm0 = fmaxf(pm0, __shfl_xor_sync(0xffffffffu, pm0, 2));
        pm1 = fmaxf(pm1, __shfl_xor_sync(0xffffffffu, pm1, 1));
        pm1 = fmaxf(pm1, __shfl_xor_sync(0xffffffffu, pm1, 2));
        if((lane&3)==0){
            redm[wc*64 + r0] = pm0;
            redm[wc*64 + r1] = pm1;
        }
        __syncthreads();
        if(tid<64){
            float mo = mrow[tid];
            float mn = fmaxf(mo, fmaxf(redm[tid], redm[64+tid]));
            arow[tid] = expf(mo - mn);
            mrow[tid] = mn;
        }
        __syncthreads();

        // ---- P = exp(S-m) -> split bf16 smem; partial sums; rescale oacc ----
        float mn0 = mrow[r0], mn1 = mrow[r1];
        float a0 = arow[r0], a1 = arow[r1];
        float rs0=0.f, rs1=0.f;
        #pragma unroll
        for(int nf=0;nf<4;nf++){
            int col = wc*32 + nf*8 + (lane&3)*2;
            float p0 = expf(sacc[nf][0]-mn0);
            float p1 = expf(sacc[nf][1]-mn0);
            float p2 = expf(sacc[nf][2]-mn1);
            float p3 = expf(sacc[nf][3]-mn1);
            rs0 += p0+p1; rs1 += p2+p3;
            uint32_t hi,lo;
            split_pair(p0,p1,hi,lo);
            *(uint32_t*)(smem + APH + r0*144 + col*2) = hi;
            *(uint32_t*)(smem + APL + r0*144 + col*2) = lo;
            split_pair(p2,p3,hi,lo);
            *(uint32_t*)(smem + APH + r1*144 + col*2) = hi;
            *(uint32_t*)(smem + APL + r1*144 + col*2) = lo;
        }
        rs0 += __shfl_xor_sync(0xffffffffu, rs0, 1);
        rs0 += __shfl_xor_sync(0xffffffffu, rs0, 2);
        rs1 += __shfl_xor_sync(0xffffffffu, rs1, 1);
        rs1 += __shfl_xor_sync(0xffffffffu, rs1, 2);
        if((lane&3)==0){
            redl[wc*64 + r0] = rs0;
            redl[wc*64 + r1] = rs1;
        }
        #pragma unroll
        for(int nf=0;nf<8;nf++){
            oacc[nf][0]*=a0; oacc[nf][1]*=a0;
            oacc[nf][2]*=a1; oacc[nf][3]*=a1;
        }
        __syncthreads();
        if(tid<64) lrow[tid] = lrow[tid]*arow[tid] + redl[tid] + redl[64+tid];

        // ---- O += P V (3xBF16) ----
        #pragma unroll
        for(int s=0;s<4;s++){
            uint32_t ph[4], pl[4];
            LDM4(ph[0],ph[1],ph[2],ph[3], pAddr + s*32);
            LDM4(pl[0],pl[1],pl[2],pl[3], pAddr + (APL-APH) + s*32);
            #pragma unroll
            for(int g=0;g<4;g++){
                uint32_t vhf[4], vlf[4];
                LDM4T(vhf[0],vhf[1],vhf[2],vhf[3], vH + vRel[g] + s*4352);
                LDM4T(vlf[0],vlf[1],vlf[2],vlf[3], vL + vRel[g] + s*4352);
                #pragma unroll
                for(int sub=0;sub<2;sub++){
                    float* C = oacc[g*2+sub];
                    mma16(C, ph[0],ph[1],ph[2],ph[3], vhf[sub*2],vhf[sub*2+1]);
                    mma16(C, ph[0],ph[1],ph[2],ph[3], vlf[sub*2],vlf[sub*2+1]);
                    mma16(C, pl[0],pl[1],pl[2],pl[3], vhf[sub*2],vhf[sub*2+1]);
                }
            }
        }
        __syncthreads();
    }

    // ---- epilogue: normalize + store packed bf16 hi/lo (out-proj A operand)
    float il0 = 1.f/lrow[r0], il1 = 1.f/lrow[r1];
    #pragma unroll
    for(int nf=0;nf<8;nf++){
        int colw = wc*32 + nf*4 + (lane&3);
        uint32_t hi,lo;
        split_pair(oacc[nf][0]*il0, oacc[nf][1]*il0, hi, lo);
        g_oh[(qbase+r0)*64 + colw] = hi;
        g_ol[(qbase+r0)*64 + colw] = lo;
        split_pair(oacc[nf][2]*il1, oacc[nf][3]*il1, hi, lo);
        g_oh[(qbase+r1)*64 + colw] = hi;
        g_ol[(qbase+r1)*64 + colw] = lo;
    }
}

// ---------------------------------------------------------------------------
extern "C" void kernel_launch(void* const* d_in, const int* in_sizes, int n_in,
                              void* d_out, int out_size){
    (void)in_sizes; (void)n_in; (void)out_size;
    const float* hs   = (const float*)d_in[0];
    const float* sim  = (const float*)d_in[1];
    const float* gates= (const float*)d_in[2];
    const float* qp   = (const float*)d_in[3];
    const float* kp   = (const float*)d_in[4];
    const float* vp   = (const float*)d_in[5];
    const float* op   = (const float*)d_in[6];
    float* out = (float*)d_out;

    cudaFuncSetAttribute(attn_tc_kernel, cudaFuncAttributeMaxDynamicSharedMemorySize, ATTN_SMEM);
    cudaFuncSetAttribute(bf16_gemm_kernel<NC,512,64,NH,1>, cudaFuncAttributeMaxDynamicSharedMemorySize, GS_TOTAL);
    cudaFuncSetAttribute(bf16_gemm_kernel<NH,64,512,NC,0>, cudaFuncAttributeMaxDynamicSharedMemorySize, GS_TOTAL);

    zero_kernel<<<2048,256>>>(out);
    prep_kernel<<<NE,256>>>(sim,gates);
    conv_w_kernel<<<4096,256>>>(qp,kp,vp,op);
    gate_kernel<<<NN,128>>>(hs);
    scan_kernel<<<1,32>>>();
    pairfill_kernel<<<NN/256,256>>>();
    bf16_gemm_kernel<NC,512,64,NH,1><<<dim3(64,3,16),256,GS_TOTAL>>>(nullptr);
    conv_qkv_kernel<<<2048,256>>>();
    attn_tc_kernel<<<dim3(NT/64,NB),256,ATTN_SMEM>>>();
    bf16_gemm_kernel<NH,64,512,NC,0><<<dim3(64,8,16),256,GS_TOTAL>>>(out);
}

// round 9
// speedup vs baseline: 3.0017x; 1.1032x over previous
#include <cuda_runtime.h>
#include <cuda_bf16.h>
#include <math.h>
#include <cstdint>

#define NB 4
#define NT 2048
#define NC 1024
#define NH 128
#define NE 16
#define NN (NB*NT)   // 8192 tokens

// ---------------- scratch (static device allocations; no runtime alloc) ----
static __device__ float g_sn[NC*NE];
static __device__ float g_sig[NE];
static __device__ int   g_nact[NN];
static __device__ unsigned char g_tok_e[NN*NE];
static __device__ float g_tok_w[NN*NE];
static __device__ int   g_cnt[NE];
static __device__ int   g_off[NE];
static __device__ int   g_cur[NE];
static __device__ int   g_pair_tok[NN*NE];
static __device__ float g_pair_w[NN*NE];
static __device__ float g_q[NN*NH];
static __device__ float g_k[NN*NH];
static __device__ float g_v[NN*NH];

// packed bf16x2 hi/lo operand arrays
static __device__ uint32_t g_xh[NN*NC/2],  g_xl[NN*NC/2];        // hidden states
static __device__ uint32_t g_wh[3*NE*NC*NH/2], g_wl[3*NE*NC*NH/2]; // q/k/v proj
static __device__ uint32_t g_oph[NE*NH*NC/2], g_opl[NE*NH*NC/2];   // o proj
static __device__ uint32_t g_qh[NN*NH/2], g_ql[NN*NH/2];
static __device__ uint32_t g_kh[NN*NH/2], g_kl[NN*NH/2];
static __device__ uint32_t g_vh[NN*NH/2], g_vl[NN*NH/2];
static __device__ uint32_t g_oh[NN*NH/2], g_ol[NN*NH/2];         // attn output

// ================= helpers ==================================================
__device__ __forceinline__ uint32_t smem_u32(const void* p){
    uint32_t a;
    asm("{ .reg .u64 t; cvta.to.shared.u64 t, %1; cvt.u32.u64 %0, t; }" : "=r"(a) : "l"(p));
    return a;
}
__device__ __forceinline__ void split_pair(float x, float y, uint32_t& hi, uint32_t& lo){
    __nv_bfloat162 h = __floats2bfloat162_rn(x, y);
    float rx = x - __low2float(h);
    float ry = y - __high2float(h);
    __nv_bfloat162 l = __floats2bfloat162_rn(rx, ry);
    hi = *(uint32_t*)&h;
    lo = *(uint32_t*)&l;
}
#define CP16(dst,src) asm volatile("cp.async.ca.shared.global [%0], [%1], 16;" :: "r"(dst), "l"(src))
#define CP_COMMIT()   asm volatile("cp.async.commit_group;" ::: "memory")
#define CP_WAIT(n)    asm volatile("cp.async.wait_group %0;" :: "n"(n) : "memory")
#define LDM4(r0,r1,r2,r3,addr) \
    asm volatile("ldmatrix.sync.aligned.m8n8.x4.shared.b16 {%0,%1,%2,%3}, [%4];" \
        : "=r"(r0),"=r"(r1),"=r"(r2),"=r"(r3) : "r"(addr))
#define LDM4T(r0,r1,r2,r3,addr) \
    asm volatile("ldmatrix.sync.aligned.m8n8.x4.trans.shared.b16 {%0,%1,%2,%3}, [%4];" \
        : "=r"(r0),"=r"(r1),"=r"(r2),"=r"(r3) : "r"(addr))
__device__ __forceinline__ void mma16(float c[4],
        uint32_t a0,uint32_t a1,uint32_t a2,uint32_t a3,
        uint32_t b0,uint32_t b1){
    asm volatile("mma.sync.aligned.m16n8k16.row.col.f32.bf16.bf16.f32 "
        "{%0,%1,%2,%3}, {%4,%5,%6,%7}, {%8,%9}, {%0,%1,%2,%3};"
        : "+f"(c[0]),"+f"(c[1]),"+f"(c[2]),"+f"(c[3])
        : "r"(a0),"r"(a1),"r"(a2),"r"(a3),"r"(b0),"r"(b1));
}

// ---------------- zero / init ----------------
__global__ void zero_kernel(float* __restrict__ out){
    long i = (long)blockIdx.x*blockDim.x + threadIdx.x;
    long stride = (long)gridDim.x*blockDim.x;
    for(long j=i;j<(long)NN*NH;j+=stride){ g_q[j]=0.f; g_k[j]=0.f; g_v[j]=0.f; }
    for(long j=i;j<(long)NN*NC;j+=stride) out[j]=0.f;
    if(i<NE) g_cnt[(int)i]=0;
}

// ---------------- sim-matrix column normalization + sigmoid(gates) ---------
__global__ void prep_kernel(const float* __restrict__ sim, const float* __restrict__ gates){
    int e = blockIdx.x;
    __shared__ float red[256];
    float ss=0.f;
    for(int c=threadIdx.x;c<NC;c+=256){ float v=sim[c*NE+e]; ss+=v*v; }
    red[threadIdx.x]=ss; __syncthreads();
    for(int s=128;s>0;s>>=1){ if(threadIdx.x<s) red[threadIdx.x]+=red[threadIdx.x+s]; __syncthreads(); }
    float inv = 1.f/fmaxf(sqrtf(red[0]),1e-12f);
    for(int c=threadIdx.x;c<NC;c+=256) g_sn[c*NE+e]=sim[c*NE+e]*inv;
    if(threadIdx.x==0) g_sig[e]=1.f/(1.f+expf(-gates[e]));
}

// ---------------- weight pre-pack (qkv proj + o proj) ----------------------
__global__ void conv_w_kernel(const float* __restrict__ qp, const float* __restrict__ kp,
                              const float* __restrict__ vp, const float* __restrict__ op){
    const long NW_QKV = (long)3*NE*NC*NH/2;
    const long NW_OP  = (long)NE*NH*NC/2;
    const long PERP   = (long)NE*NC*NH/2;
    long stride = (long)gridDim.x*blockDim.x;
    for(long idx = (long)blockIdx.x*blockDim.x + threadIdx.x; idx < NW_QKV+NW_OP; idx += stride){
        uint32_t hi,lo;
        if(idx < NW_QKV){
            long p = idx / PERP;
            long r = idx - p*PERP;
            const float* src = (p==0? qp : (p==1? kp : vp)) + r*2;
            float2 v = *(const float2*)src;
            split_pair(v.x,v.y,hi,lo);
            g_wh[idx]=hi; g_wl[idx]=lo;
        } else {
            long r = idx - NW_QKV;
            float2 v = *(const float2*)(op + r*2);
            split_pair(v.x,v.y,hi,lo);
            g_oph[r]=hi; g_opl[r]=lo;
        }
    }
}

// ---------------- gating v2: smem-cached sim matrix ------------------------
// CTA = 64 tokens x 4 parts (256 thr). sim staged transposed in smem:
// section p (c in [p*256,(p+1)*256)): sns[p*4104 + e*256 + cc], +8-word skew
// per section -> warp LDS.128 across 4 parts hits banks {0-3,8-11,16-19,24-27}.
#define GT2_SECT 4104
#define GT2_SMEM (4*GT2_SECT*4)   // 65664 bytes

__global__ void __launch_bounds__(256) gate2_kernel(const float* __restrict__ X){
    extern __shared__ float sns[];
    int tid = threadIdx.x;
    // stage + transpose sim matrix (reads coalesced)
    for(int i=tid; i<NC*NE; i+=256){
        int c = i>>4, e = i&15;
        sns[(c>>8)*GT2_SECT + e*256 + (c&255)] = g_sn[i];
    }
    __syncthreads();

    int part = tid&3, tl = tid>>2;
    int token = blockIdx.x*64 + tl;
    const float4* x4 = (const float4*)(X + (long)token*NC + part*256);
    const float* snp = sns + part*GT2_SECT;
    long xw = (long)token*(NC/2) + part*128;

    float ssq = 0.f, dot[NE];
    #pragma unroll
    for(int e=0;e<NE;e++) dot[e]=0.f;

    #pragma unroll 4
    for(int cb=0; cb<64; cb++){
        float4 xv = x4[cb];
        ssq += xv.x*xv.x + xv.y*xv.y + xv.z*xv.z + xv.w*xv.w;
        uint32_t h0,l0,h1,l1;
        split_pair(xv.x,xv.y,h0,l0);
        split_pair(xv.z,xv.w,h1,l1);
        g_xh[xw + cb*2    ] = h0;  g_xl[xw + cb*2    ] = l0;
        g_xh[xw + cb*2 + 1] = h1;  g_xl[xw + cb*2 + 1] = l1;
        #pragma unroll
        for(int e=0;e<NE;e++){
            float4 s = *(const float4*)(snp + e*256 + cb*4);
            dot[e] += xv.x*s.x + xv.y*s.y + xv.z*s.z + xv.w*s.w;
        }
    }
    // butterfly over the 4 parts (adjacent lanes)
    #pragma unroll
    for(int off=1; off<4; off<<=1){
        ssq += __shfl_xor_sync(0xffffffffu, ssq, off);
        #pragma unroll
        for(int e=0;e<NE;e++) dot[e] += __shfl_xor_sync(0xffffffffu, dot[e], off);
    }
    if(part==0){
        float inv = 1.f/fmaxf(sqrtf(ssq),1e-12f);
        float logit[NE];
        #pragma unroll
        for(int e=0;e<NE;e++) logit[e] = dot[e]*inv - g_sig[e];
        int act[NE]; int na=0;
        for(int e=0;e<NE;e++) if(logit[e]>0.f) act[na++]=e;
        if(na==0){
            int i1=0;
            for(int e=1;e<NE;e++) if(logit[e]>logit[i1]) i1=e;
            int i2=-1;
            for(int e=0;e<NE;e++) if(e!=i1 && (i2<0 || logit[e]>logit[i2])) i2=e;
            int a = i1<i2? i1:i2; int b2 = i1<i2? i2:i1;
            act[0]=a; act[1]=b2; na=2;
        }
        float vals[NE]; float mx=-1e30f;
        for(int k=0;k<na;k++){ vals[k]=fmaxf(logit[act[k]],0.f); mx=fmaxf(mx,vals[k]); }
        float sum=0.f;
        for(int k=0;k<na;k++){ vals[k]=expf(vals[k]-mx); sum+=vals[k]; }
        float isum = 1.f/sum;
        g_nact[token]=na;
        for(int k=0;k<na;k++){
            g_tok_e[token*NE+k]=(unsigned char)act[k];
            g_tok_w[token*NE+k]=vals[k]*isum;
            atomicAdd(&g_cnt[act[k]],1);
        }
    }
}

__global__ void scan_kernel(){
    if(threadIdx.x==0){
        int o=0;
        for(int e=0;e<NE;e++){ g_off[e]=o; o+=g_cnt[e]; }
    }
    if(threadIdx.x<NE) g_cur[threadIdx.x]=0;
}

__global__ void pairfill_kernel(){
    int n = blockIdx.x*blockDim.x + threadIdx.x;
    if(n>=NN) return;
    int na=g_nact[n];
    for(int k=0;k<na;k++){
        int e=g_tok_e[n*NE+k];
        int s=atomicAdd(&g_cur[e],1);
        int p=g_off[e]+s;
        g_pair_tok[p]=n;
        g_pair_w[p]=g_tok_w[n*NE+k];
    }
}

// ---------------- q/k/v fp32 -> packed bf16 hi/lo (Q pre-scaled) -----------
__global__ void conv_qkv_kernel(){
    const float scale = 0.0883883476483184f;  // 1/sqrt(128)
    long idx = (long)blockIdx.x*blockDim.x + threadIdx.x;  // word index < NN*NH/2
    if(idx >= (long)NN*NH/2) return;
    uint32_t hi,lo;
    float2 q = *(const float2*)(g_q + idx*2);
    split_pair(q.x*scale, q.y*scale, hi, lo);
    g_qh[idx]=hi; g_ql[idx]=lo;
    float2 k = *(const float2*)(g_k + idx*2);
    split_pair(k.x, k.y, hi, lo);
    g_kh[idx]=hi; g_kl[idx]=lo;
    float2 v = *(const float2*)(g_v + idx*2);
    split_pair(v.x, v.y, hi, lo);
    g_vh[idx]=hi; g_vl[idx]=lo;
}

// =============== 3xBF16 m16n8k16 grouped GEMM, cp.async pipelined ==========
#define GS_TOK 0
#define GS_W   512
#define GS_A   1024
#define GS_ABUF 10240
#define GS_B   (GS_A + 4*GS_ABUF)      // 41984
#define GS_BBUF 8704
#define GS_TOTAL (GS_B + 4*GS_BBUF)    // 76800

template<int KTOT, int LDAW, int LDBW, int LDO, int QKV>
__global__ void __launch_bounds__(256) bf16_gemm_kernel(float* __restrict__ OutP){
    int e = blockIdx.z;
    int cnt = g_cnt[e];
    int m0 = blockIdx.x*128;
    if(m0>=cnt) return;
    int off = g_off[e];

    const uint32_t *Axh, *Axl, *Bh, *Bl;
    float* Out; int n0;
    if(QKV){
        Axh = g_xh; Axl = g_xl;
        long woff = ((long)blockIdx.y*NE + e)*NC*(NH/2);
        Bh = g_wh + woff; Bl = g_wl + woff;
        Out = (blockIdx.y==0)? g_q : (blockIdx.y==1? g_k : g_v);
        n0 = 0;
    } else {
        Axh = g_oh; Axl = g_ol;
        long woff = (long)e*NH*(NC/2);
        Bh = g_oph + woff; Bl = g_opl + woff;
        Out = OutP;
        n0 = blockIdx.y*128;
    }
    int n0w = n0/2;

    extern __shared__ __align__(16) char smem[];
    uint32_t sb = smem_u32(smem);
    int*   stok = (int*)(smem + GS_TOK);
    float* sw   = (float*)(smem + GS_W);

    int tid=threadIdx.x, lane=tid&31, wid=tid>>5;
    int wr = wid>>2, wc = wid&3;

    if(tid<128){
        int m=m0+tid; int mm = m<cnt? m : cnt-1;
        stok[tid]=g_pair_tok[off+mm];
        sw[tid]= (m<cnt)? g_pair_w[off+mm] : 0.f;
    }
    __syncthreads();

    // prefetch assignments
    int ar = tid>>1, ahalf = tid&1;
    const uint32_t* ash = Axh + (long)stok[ar]*LDAW + ahalf*8;
    const uint32_t* asl = Axl + (long)stok[ar]*LDAW + ahalf*8;
    uint32_t adst = sb + GS_A + ar*80 + ahalf*32;
    int bk = tid>>3, bn = (tid&7)*8;
    const uint32_t* bsh = Bh + (long)bk*LDBW + n0w + bn;
    const uint32_t* bsl = Bl + (long)bk*LDBW + n0w + bn;
    uint32_t bdst = sb + GS_B + bk*272 + bn*4;

    const int NCH = KTOT/32;

    int mid = lane>>3, l7 = lane&7;
    uint32_t aRel[4];
    #pragma unroll
    for(int mf=0;mf<4;mf++){
        int row = wr*64 + mf*16 + (mid&1)*8 + l7;
        aRel[mf] = row*80 + (mid>>1)*16;
    }
    uint32_t bRel[2];
    #pragma unroll
    for(int g=0;g<2;g++){
        int krow = (mid&1)*8 + l7;
        int ncol = wc*32 + g*16 + (mid>>1)*8;
        bRel[g] = krow*272 + ncol*2;
    }

    float acc[4][4][4];
    #pragma unroll
    for(int mf=0;mf<4;mf++)
        #pragma unroll
        for(int nf=0;nf<4;nf++)
            #pragma unroll
            for(int u=0;u<4;u++) acc[mf][nf][u]=0.f;

    {
        CP16(adst,               ash);
        CP16(adst+16,            ash+4);
        CP16(adst+GS_ABUF,       asl);
        CP16(adst+GS_ABUF+16,    asl+4);
        CP16(bdst,               bsh);
        CP16(bdst+16,            bsh+4);
        CP16(bdst+GS_BBUF,       bsl);
        CP16(bdst+GS_BBUF+16,    bsl+4);
        CP_COMMIT();
    }

    for(int c=0;c<NCH;c++){
        if(c+1<NCH){
            int st = (c+1)&1;
            uint32_t ad = adst + st*(2*GS_ABUF);
            uint32_t bd = bdst + st*(2*GS_BBUF);
            const uint32_t* ash2 = ash + (c+1)*16;
            const uint32_t* asl2 = asl + (c+1)*16;
            const uint32_t* bsh2 = bsh + (long)(c+1)*32*LDBW;
            const uint32_t* bsl2 = bsl + (long)(c+1)*32*LDBW;
            CP16(ad,            ash2);
            CP16(ad+16,         ash2+4);
            CP16(ad+GS_ABUF,    asl2);
            CP16(ad+GS_ABUF+16, asl2+4);
            CP16(bd,            bsh2);
            CP16(bd+16,         bsh2+4);
            CP16(bd+GS_BBUF,    bsl2);
            CP16(bd+GS_BBUF+16, bsl2+4);
            CP_COMMIT();
            CP_WAIT(1);
        } else {
            CP_WAIT(0);
        }
        __syncthreads();

        uint32_t stA = sb + GS_A + (c&1)*(2*GS_ABUF);
        uint32_t stB = sb + GS_B + (c&1)*(2*GS_BBUF);

        #pragma unroll
        for(int s=0;s<2;s++){
            uint32_t ahh[4][4], alo[4][4];
            #pragma unroll
            for(int mf=0;mf<4;mf++){
                LDM4(ahh[mf][0],ahh[mf][1],ahh[mf][2],ahh[mf][3], stA + aRel[mf] + s*32);
                LDM4(alo[mf][0],alo[mf][1],alo[mf][2],alo[mf][3], stA + GS_ABUF + aRel[mf] + s*32);
            }
            #pragma unroll
            for(int g=0;g<2;g++){
                uint32_t bh[4], bl[4];
                LDM4T(bh[0],bh[1],bh[2],bh[3], stB + bRel[g] + s*4352);
                LDM4T(bl[0],bl[1],bl[2],bl[3], stB + GS_BBUF + bRel[g] + s*4352);
                #pragma unroll
                for(int sub=0;sub<2;sub++){
                    #pragma unroll
                    for(int mf=0;mf<4;mf++){
                        float* C = acc[mf][g*2+sub];
                        mma16(C, ahh[mf][0],ahh[mf][1],ahh[mf][2],ahh[mf][3], bh[sub*2],bh[sub*2+1]);
                        mma16(C, ahh[mf][0],ahh[mf][1],ahh[mf][2],ahh[mf][3], bl[sub*2],bl[sub*2+1]);
                        mma16(C, alo[mf][0],alo[mf][1],alo[mf][2],alo[mf][3], bh[sub*2],bh[sub*2+1]);
                    }
                }
            }
        }
        __syncthreads();
    }

    #pragma unroll
    for(int mf=0;mf<4;mf++){
        int r0 = wr*64 + mf*16 + (lane>>2);
        int r1 = r0 + 8;
        float w0 = sw[r0], w1 = sw[r1];
        int live0 = (m0 + r0 < cnt), live1 = (m0 + r1 < cnt);
        long b0 = (long)stok[r0]*LDO + n0;
        long b1 = (long)stok[r1]*LDO + n0;
        #pragma unroll
        for(int nf=0;nf<4;nf++){
            int col = wc*32 + nf*8 + (lane&3)*2;
            if(live0){
                atomicAdd(&Out[b0 + col    ], acc[mf][nf][0]*w0);
                atomicAdd(&Out[b0 + col + 1], acc[mf][nf][1]*w0);
            }
            if(live1){
                atomicAdd(&Out[b1 + col    ], acc[mf][nf][2]*w1);
                atomicAdd(&Out[b1 + col + 1], acc[mf][nf][3]*w1);
            }
        }
    }
}

// ------------- flash attention, 3xBF16 mma + ldmatrix + cp.async -----------
#define AQH 0
#define AQL 17408
#define AKV0 34816
#define AKV1 104448
#define AKVST 17408
#define APH 174080
#define APL 183296
#define AREDM 192512
#define AREDL 193024
#define AMROW 193536
#define ALROW 193792
#define AAROW 194048
#define ATTN_SMEM 194304

__global__ void __launch_bounds__(256) attn_tc_kernel(){
    extern __shared__ __align__(16) char smem[];
    uint32_t sb = smem_u32(smem);
    float* redm = (float*)(smem + AREDM);
    float* redl = (float*)(smem + AREDL);
    float* mrow = (float*)(smem + AMROW);
    float* lrow = (float*)(smem + ALROW);
    float* arow = (float*)(smem + AAROW);

    int b = blockIdx.y, qt = blockIdx.x;
    int tid = threadIdx.x, lane = tid&31, wid = tid>>5;
    int wr = wid>>1, wc = wid&1;
    long qbase = (long)b*NT + (long)qt*64;

    int lr = tid>>2, lq = tid&3;
    uint32_t ldst = lr*272 + lq*64;

    {
        const uint32_t* qh = g_qh + (qbase+lr)*64 + lq*16;
        const uint32_t* ql = g_ql + (qbase+lr)*64 + lq*16;
        #pragma unroll
        for(int q=0;q<4;q++){
            CP16(sb + AQH + ldst + q*16, qh + q*4);
            CP16(sb + AQL + ldst + q*16, ql + q*4);
        }
        long kb = (long)b*NT;
        const uint32_t* kh = g_kh + (kb+lr)*64 + lq*16;
        const uint32_t* kl = g_kl + (kb+lr)*64 + lq*16;
        const uint32_t* vh = g_vh + (kb+lr)*64 + lq*16;
        const uint32_t* vl = g_vl + (kb+lr)*64 + lq*16;
        #pragma unroll
        for(int q=0;q<4;q++){
            CP16(sb + AKV0 + 0*AKVST + ldst + q*16, kh + q*4);
            CP16(sb + AKV0 + 1*AKVST + ldst + q*16, kl + q*4);
            CP16(sb + AKV0 + 2*AKVST + ldst + q*16, vh + q*4);
            CP16(sb + AKV0 + 3*AKVST + ldst + q*16, vl + q*4);
        }
        CP_COMMIT();
    }
    if(tid<64){ mrow[tid]=-INFINITY; lrow[tid]=0.f; }

    float oacc[8][4];
    #pragma unroll
    for(int nf=0;nf<8;nf++)
        #pragma unroll
        for(int u=0;u<4;u++) oacc[nf][u]=0.f;

    int r0 = wr*16 + (lane>>2), r1 = r0+8;

    int mid = lane>>3, l7 = lane&7;
    uint32_t qAddr, pAddr, kRel[2], vRel[4];
    {
        int row = wr*16 + (mid&1)*8 + l7;
        qAddr = sb + AQH + row*272 + (mid>>1)*16;
        pAddr = sb + APH + row*144 + (mid>>1)*16;
        #pragma unroll
        for(int g=0;g<2;g++){
            int n = wc*32 + g*16 + (mid>>1)*8 + l7;
            kRel[g] = n*272 + (mid&1)*16;
        }
        #pragma unroll
        for(int g=0;g<4;g++){
            int krow = (mid&1)*8 + l7;
            int ncol = wc*64 + g*16 + (mid>>1)*8;
            vRel[g] = krow*272 + ncol*2;
        }
    }

    for(int kt=0; kt<NT/64; kt++){
        if(kt+1 < NT/64){
            uint32_t base = sb + (((kt+1)&1) ? AKV1 : AKV0);
            long kb = (long)b*NT + (long)(kt+1)*64;
            const uint32_t* kh = g_kh + (kb+lr)*64 + lq*16;
            const uint32_t* kl = g_kl + (kb+lr)*64 + lq*16;
            const uint32_t* vh = g_vh + (kb+lr)*64 + lq*16;
            const uint32_t* vl = g_vl + (kb+lr)*64 + lq*16;
            #pragma unroll
            for(int q=0;q<4;q++){
                CP16(base + 0*AKVST + ldst + q*16, kh + q*4);
                CP16(base + 1*AKVST + ldst + q*16, kl + q*4);
                CP16(base + 2*AKVST + ldst + q*16, vh + q*4);
                CP16(base + 3*AKVST + ldst + q*16, vl + q*4);
            }
            CP_COMMIT();
            CP_WAIT(1);
        } else {
            CP_WAIT(0);
        }
        __syncthreads();

        uint32_t kvb = sb + ((kt&1) ? AKV1 : AKV0);
        uint32_t kH = kvb, kL = kvb + AKVST, vH = kvb + 2*AKVST, vL = kvb + 3*AKVST;

        float sacc[4][4];
        #pragma unroll
        for(int nf=0;nf<4;nf++)
            #pragma unroll
            for(int u=0;u<4;u++) sacc[nf][u]=0.f;

        #pragma unroll
        for(int s=0;s<8;s++){
            uint32_t qh[4], ql[4];
            LDM4(qh[0],qh[1],qh[2],qh[3], qAddr + s*32);
            LDM4(ql[0],ql[1],ql[2],ql[3], qAddr + (AQL-AQH) + s*32);
            #pragma unroll
            for(int g=0;g<2;g++){
                uint32_t khf[4], klf[4];
                LDM4(khf[0],khf[1],khf[2],khf[3], kH + kRel[g] + s*32);
                LDM4(klf[0],klf[1],klf[2],klf[3], kL + kRel[g] + s*32);
                #pragma unroll
                for(int sub=0;sub<2;sub++){
                    float* C = sacc[g*2+sub];
                    mma16(C, qh[0],qh[1],qh[2],qh[3], khf[sub*2],khf[sub*2+1]);
                    mma16(C, qh[0],qh[1],qh[2],qh[3], klf[sub*2],klf[sub*2+1]);
                    mma16(C, ql[0],ql[1],ql[2],ql[3], khf[sub*2],khf[sub*2+1]);
                }
            }
        }

        float pm0 = fmaxf(fmaxf(sacc[0][0],sacc[0][1]), fmaxf(sacc[1][0],sacc[1][1]));
        pm0 = fmaxf(pm0, fmaxf(fmaxf(sacc[2][0],sacc[2][1]), fmaxf(sacc[3][0],sacc[3][1])));
        float pm1 = fmaxf(fmaxf(sacc[0][2],sacc[0][3]), fmaxf(sacc[1][2],sacc[1][3]));
        pm1 = fmaxf(pm1, fmaxf(fmaxf(sacc[2][2],sacc[2][3]), fmaxf(sacc[3][2],sacc[3][3])));
        pm0 = fmaxf(pm0, __shfl_xor_sync(0xffffffffu, pm0, 1));
        pm0 = fmaxf(pm0, __shfl_xor_sync(0xffffffffu, pm0, 2));
        pm1 = fmaxf(pm1, __shfl_xor_sync(0xffffffffu, pm1, 1));
        pm1 = fmaxf(pm1, __shfl_xor_sync(0xffffffffu, pm1, 2));
        if((lane&3)==0){
            redm[wc*64 + r0] = pm0;
            redm[wc*64 + r1] = pm1;
        }
        __syncthreads();
        if(tid<64){
            float mo = mrow[tid];
            float mn = fmaxf(mo, fmaxf(redm[tid], redm[64+tid]));
            arow[tid] = expf(mo - mn);
            mrow[tid] = mn;
        }
        __syncthreads();

        float mn0 = mrow[r0], mn1 = mrow[r1];
        float a0 = arow[r0], a1 = arow[r1];
        float rs0=0.f, rs1=0.f;
        #pragma unroll
        for(int nf=0;nf<4;nf++){
            int col = wc*32 + nf*8 + (lane&3)*2;
            float p0 = expf(sacc[nf][0]-mn0);
            float p1 = expf(sacc[nf][1]-mn0);
            float p2 = expf(sacc[nf][2]-mn1);
            float p3 = expf(sacc[nf][3]-mn1);
            rs0 += p0+p1; rs1 += p2+p3;
            uint32_t hi,lo;
            split_pair(p0,p1,hi,lo);
            *(uint32_t*)(smem + APH + r0*144 + col*2) = hi;
            *(uint32_t*)(smem + APL + r0*144 + col*2) = lo;
            split_pair(p2,p3,hi,lo);
            *(uint32_t*)(smem + APH + r1*144 + col*2) = hi;
            *(uint32_t*)(smem + APL + r1*144 + col*2) = lo;
        }
        rs0 += __shfl_xor_sync(0xffffffffu, rs0, 1);
        rs0 += __shfl_xor_sync(0xffffffffu, rs0, 2);
        rs1 += __shfl_xor_sync(0xffffffffu, rs1, 1);
        rs1 += __shfl_xor_sync(0xffffffffu, rs1, 2);
        if((lane&3)==0){
            redl[wc*64 + r0] = rs0;
            redl[wc*64 + r1] = rs1;
        }
        #pragma unroll
        for(int nf=0;nf<8;nf++){
            oacc[nf][0]*=a0; oacc[nf][1]*=a0;
            oacc[nf][2]*=a1; oacc[nf][3]*=a1;
        }
        __syncthreads();
        if(tid<64) lrow[tid] = lrow[tid]*arow[tid] + redl[tid] + redl[64+tid];

        #pragma unroll
        for(int s=0;s<4;s++){
            uint32_t ph[4], pl[4];
            LDM4(ph[0],ph[1],ph[2],ph[3], pAddr + s*32);
            LDM4(pl[0],pl[1],pl[2],pl[3], pAddr + (APL-APH) + s*32);
            #pragma unroll
            for(int g=0;g<4;g++){
                uint32_t vhf[4], vlf[4];
                LDM4T(vhf[0],vhf[1],vhf[2],vhf[3], vH + vRel[g] + s*4352);
                LDM4T(vlf[0],vlf[1],vlf[2],vlf[3], vL + vRel[g] + s*4352);
                #pragma unroll
                for(int sub=0;sub<2;sub++){
                    float* C = oacc[g*2+sub];
                    mma16(C, ph[0],ph[1],ph[2],ph[3], vhf[sub*2],vhf[sub*2+1]);
                    mma16(C, ph[0],ph[1],ph[2],ph[3], vlf[sub*2],vlf[sub*2+1]);
                    mma16(C, pl[0],pl[1],pl[2],pl[3], vhf[sub*2],vhf[sub*2+1]);
                }
            }
        }
        __syncthreads();
    }

    float il0 = 1.f/lrow[r0], il1 = 1.f/lrow[r1];
    #pragma unroll
    for(int nf=0;nf<8;nf++){
        int colw = wc*32 + nf*4 + (lane&3);
        uint32_t hi,lo;
        split_pair(oacc[nf][0]*il0, oacc[nf][1]*il0, hi, lo);
        g_oh[(qbase+r0)*64 + colw] = hi;
        g_ol[(qbase+r0)*64 + colw] = lo;
        split_pair(oacc[nf][2]*il1, oacc[nf][3]*il1, hi, lo);
        g_oh[(qbase+r1)*64 + colw] = hi;
        g_ol[(qbase+r1)*64 + colw] = lo;
    }
}

// ---------------------------------------------------------------------------
extern "C" void kernel_launch(void* const* d_in, const int* in_sizes, int n_in,
                              void* d_out, int out_size){
    (void)in_sizes; (void)n_in; (void)out_size;
    const float* hs   = (const float*)d_in[0];
    const float* sim  = (const float*)d_in[1];
    const float* gates= (const float*)d_in[2];
    const float* qp   = (const float*)d_in[3];
    const float* kp   = (const float*)d_in[4];
    const float* vp   = (const float*)d_in[5];
    const float* op   = (const float*)d_in[6];
    float* out = (float*)d_out;

    cudaFuncSetAttribute(attn_tc_kernel, cudaFuncAttributeMaxDynamicSharedMemorySize, ATTN_SMEM);
    cudaFuncSetAttribute(bf16_gemm_kernel<NC,512,64,NH,1>, cudaFuncAttributeMaxDynamicSharedMemorySize, GS_TOTAL);
    cudaFuncSetAttribute(bf16_gemm_kernel<NH,64,512,NC,0>, cudaFuncAttributeMaxDynamicSharedMemorySize, GS_TOTAL);
    cudaFuncSetAttribute(gate2_kernel, cudaFuncAttributeMaxDynamicSharedMemorySize, GT2_SMEM);

    zero_kernel<<<2048,256>>>(out);
    prep_kernel<<<NE,256>>>(sim,gates);
    conv_w_kernel<<<4096,256>>>(qp,kp,vp,op);
    gate2_kernel<<<NN/64,256,GT2_SMEM>>>(hs);
    scan_kernel<<<1,32>>>();
    pairfill_kernel<<<NN/256,256>>>();
    bf16_gemm_kernel<NC,512,64,NH,1><<<dim3(64,3,16),256,GS_TOTAL>>>(nullptr);
    conv_qkv_kernel<<<2048,256>>>();
    attn_tc_kernel<<<dim3(NT/64,NB),256,ATTN_SMEM>>>();
    bf16_gemm_kernel<NH,64,512,NC,0><<<dim3(64,8,16),256,GS_TOTAL>>>(out);
}